// round 10
// baseline (speedup 1.0000x reference)
#include <cuda_runtime.h>
#include <cuda_bf16.h>
#include <math.h>

// ---------------- problem constants ----------------
#define GX 116
#define GY 87
#define BATCH 4
#define NSEG (BATCH * GX * GY)          // 40368
#define MAXN 1000000
#define C0 32
#define C1 128
#define EPSB 0.001f
#define PAD 68                           // floats per channel row (64 pts + pad)
#define NBLK 592

typedef unsigned long long ull;

// ---------------- scratch (__device__ globals; no allocation) ----------------
__device__ int      g_inv[MAXN];
__device__ int      g_rank[MAXN];
__device__ float4   g_feat[MAXN];        // segment-sorted packed features
__device__ int      g_sseg[MAXN];        // sorted segment id per point
__device__ int      g_cnt[NSEG];
__device__ int      g_off[NSEG];
__device__ unsigned g_h0min[NSEG * C0];  // encoded order-preserving uint
__device__ unsigned g_h0max[NSEG * C0];
__device__ float    g_amin[NSEG * C1];   // exclusive-owner plain floats
__device__ float    g_amax[NSEG * C1];
__device__ float    g_asum[NSEG * C1];
__device__ float    g_m0[NSEG * C0];
__device__ float    g_min1[NSEG * C1];
__device__ float    g_max1[NSEG * C1];
__device__ double   g_mom[14];
__device__ double   g_s1[C1];
__device__ double   g_ss1[C1];
__device__ float    g_a0[C0], g_c0[C0];
__device__ float    g_a1[C1], g_c1[C1];
__device__ float    g_dense[BATCH * C1 * GY * GX];

// ---------------- helpers ----------------
__device__ __forceinline__ float swishf(float x) {
    return __fdividef(x, 1.0f + __expf(-x));
}
__device__ __forceinline__ float swish_seg_max(float pmin, float pmax, float a, float c) {
    return fmaxf(swishf(a * pmin + c), swishf(a * pmax + c));
}
__device__ __forceinline__ unsigned encf(float x) {
    unsigned u = __float_as_uint(x);
    return (u & 0x80000000u) ? ~u : (u | 0x80000000u);
}
__device__ __forceinline__ float decf(unsigned e) {
    unsigned u = (e & 0x80000000u) ? (e & 0x7FFFFFFFu) : ~e;
    return __uint_as_float(u);
}
__device__ __forceinline__ ull pk2(float lo, float hi) {
    ull r; asm("mov.b64 %0, {%1,%2};" : "=l"(r) : "f"(lo), "f"(hi)); return r;
}
__device__ __forceinline__ void upk2(ull v, float& lo, float& hi) {
    asm("mov.b64 {%0,%1}, %2;" : "=f"(lo), "=f"(hi) : "l"(v));
}
__device__ __forceinline__ ull fma2(ull a, ull b, ull c) {
    ull d; asm("fma.rn.f32x2 %0, %1, %2, %3;" : "=l"(d) : "l"(a), "l"(b), "l"(c)); return d;
}
__device__ __forceinline__ ull add2(ull a, ull b) {
    ull d; asm("add.rn.f32x2 %0, %1, %2;" : "=l"(d) : "l"(a), "l"(b)); return d;
}

template<int J>
__device__ __forceinline__ void bloop(unsigned base, const ull (&wp)[32], ull& acc01, ull& acc23) {
    if constexpr (J < 32) {
        ull h01, h23;
        asm volatile("ld.shared.v2.u64 {%0,%1}, [%2+%3];"
                     : "=l"(h01), "=l"(h23) : "r"(base), "n"(J * PAD * 4));
        acc01 = fma2(h01, wp[J], acc01);
        acc23 = fma2(h23, wp[J], acc23);
        bloop<J + 1>(base, wp, acc01, acc23);
    }
}

// ---------------- init ----------------
__global__ void k_init() {
    int i = blockIdx.x * blockDim.x + threadIdx.x;
    if (i < NSEG * C0) { g_h0min[i] = 0xFFFFFFFFu; g_h0max[i] = 0u; }
    if (i < NSEG) g_cnt[i] = 0;
    if (i < 14)   g_mom[i] = 0.0;
    if (i < C1)   { g_s1[i] = 0.0; g_ss1[i] = 0.0; }
}

// ---------------- P1: inv, rank, histogram, feature moments ----------------
__global__ void k_p1(const float* __restrict__ pts, int N) {
    __shared__ double smom[14];
    if (threadIdx.x < 14) smom[threadIdx.x] = 0.0;
    __syncthreads();

    int i = blockIdx.x * blockDim.x + threadIdx.x;
    float m[14];
#pragma unroll
    for (int k = 0; k < 14; k++) m[k] = 0.0f;

    if (i < N) {
        const float* p = pts + (size_t)i * 5;
        float b = p[0], x = p[1], y = p[2], t = p[3], pol = p[4];
        int cx = (int)floorf(x / 3.0f);
        int cy = (int)floorf(y / 3.0f);
        int bi = (int)b;
        int inv = (bi * GX + cx) * GY + cy;
        g_inv[i] = inv;
        g_rank[i] = atomicAdd(&g_cnt[inv], 1);
        float f0 = x / 346.0f, f1 = y / 260.0f, f2 = t / 200.0f, f3 = pol;
        m[0] = f0; m[1] = f1; m[2] = f2; m[3] = f3;
        m[4] = f0 * f0; m[5] = f0 * f1; m[6] = f0 * f2; m[7] = f0 * f3;
        m[8] = f1 * f1; m[9] = f1 * f2; m[10] = f1 * f3;
        m[11] = f2 * f2; m[12] = f2 * f3; m[13] = f3 * f3;
    }

#pragma unroll
    for (int k = 0; k < 14; k++) {
#pragma unroll
        for (int off = 16; off > 0; off >>= 1)
            m[k] += __shfl_down_sync(0xFFFFFFFFu, m[k], off);
    }
    if ((threadIdx.x & 31) == 0) {
#pragma unroll
        for (int k = 0; k < 14; k++) atomicAdd(&smom[k], (double)m[k]);
    }
    __syncthreads();
    if (threadIdx.x < 14) atomicAdd(&g_mom[threadIdx.x], smom[threadIdx.x]);
}

// ---------------- scan ----------------
__global__ void k_scan() {
    __shared__ int partial[1024];
    const int PER = (NSEG + 1023) / 1024;
    int tid = threadIdx.x;
    int base = tid * PER;
    int s = 0;
    for (int k = 0; k < PER; k++) {
        int idx = base + k;
        if (idx < NSEG) s += g_cnt[idx];
    }
    partial[tid] = s;
    __syncthreads();
    for (int d = 1; d < 1024; d <<= 1) {
        int v = partial[tid];
        int add = (tid >= d) ? partial[tid - d] : 0;
        __syncthreads();
        partial[tid] = v + add;
        __syncthreads();
    }
    int run = (tid == 0) ? 0 : partial[tid - 1];
    for (int k = 0; k < PER; k++) {
        int idx = base + k;
        if (idx < NSEG) {
            g_off[idx] = run;
            run += g_cnt[idx];
        }
    }
}

// ---------------- S0: bn0 affine ----------------
__global__ void k_s0(const float* __restrict__ W0, const float* __restrict__ g0,
                     const float* __restrict__ b0, int N) {
    int ch = threadIdx.x;
    if (ch >= C0) return;
    double s0 = g_mom[0], s1 = g_mom[1], s2 = g_mom[2], s3 = g_mom[3];
    double M00 = g_mom[4], M01 = g_mom[5], M02 = g_mom[6], M03 = g_mom[7];
    double M11 = g_mom[8], M12 = g_mom[9], M13 = g_mom[10];
    double M22 = g_mom[11], M23 = g_mom[12], M33 = g_mom[13];
    double w0 = W0[ch], w1 = W0[C0 + ch], w2 = W0[2 * C0 + ch], w3 = W0[3 * C0 + ch];
    double dN = (double)N;
    double mu = (s0 * w0 + s1 * w1 + s2 * w2 + s3 * w3) / dN;
    double ex2 = (M00 * w0 * w0 + M11 * w1 * w1 + M22 * w2 * w2 + M33 * w3 * w3
                  + 2.0 * (M01 * w0 * w1 + M02 * w0 * w2 + M03 * w0 * w3
                           + M12 * w1 * w2 + M13 * w1 * w3 + M23 * w2 * w3)) / dN;
    double var = ex2 - mu * mu;
    double a = (double)g0[ch] / sqrt(var + (double)EPSB);
    g_a0[ch] = (float)a;
    g_c0[ch] = (float)((double)b0[ch] - mu * a);
}

// ---------------- scatter (no atomics) ----------------
__global__ void k_scatter(const float* __restrict__ pts, int N) {
    int i = blockIdx.x * blockDim.x + threadIdx.x;
    if (i >= N) return;
    const float* p = pts + (size_t)i * 5;
    float x = p[1], y = p[2], t = p[3], pol = p[4];
    int inv = g_inv[i];
    int pos = g_off[inv] + g_rank[i];
    g_feat[pos] = make_float4(x / 346.0f, y / 260.0f, t / 200.0f, pol);
    g_sseg[pos] = inv;
}

// ---------------- streaming pass: contiguous segment ownership, no flush atomics (B) ----------------
__global__ void __launch_bounds__(C1, 4)
k_seg(const float* __restrict__ W0, const float* __restrict__ W1, int N) {
    int tid = threadIdx.x, c = tid & 31, row = tid >> 5;

    ull wp[32];
#pragma unroll
    for (int j = 0; j < 32; j++) {
        float v = W1[j * C1 + tid];
        wp[j] = pk2(v, v);
    }
    float w00 = W0[c], w01 = W0[C0 + c], w02 = W0[2 * C0 + c], w03 = W0[3 * C0 + c];
    float a0 = g_a0[c], c0 = g_c0[c];

    __shared__ __align__(16) float h0s[2][C0 * PAD];
    __shared__ __align__(16) int ss[2][64];
    unsigned h0base0 = (unsigned)__cvta_generic_to_shared(&h0s[0][0]);

    // contiguous segment range owned by this block
    long long T0 = (long long)blockIdx.x * N / gridDim.x;
    long long T1 = (long long)(blockIdx.x + 1) * N / gridDim.x;
    int lo = 0, hi = NSEG;
    while (lo < hi) { int mid = (lo + hi) >> 1; if ((long long)g_off[mid] < T0) lo = mid + 1; else hi = mid; }
    int s_begin = lo;
    hi = NSEG;
    while (lo < hi) { int mid = (lo + hi) >> 1; if ((long long)g_off[mid] < T1) lo = mid + 1; else hi = mid; }
    int s_end = lo;
    int P0 = (s_begin < NSEG) ? g_off[s_begin] : N;
    int P1 = (s_end   < NSEG) ? g_off[s_end]   : N;

    // phase A running state (channel c)
    int curA = -1; float lmin = 0.0f, lmax = 0.0f;
    // phase B running state (out channel tid) — exclusive owner => plain stores
    int curB = -1; float rmin = 0.0f, rmax = 0.0f, rsum = 0.0f;
    double dsum = 0.0, dssq = 0.0;
    int buf = 0;
    __syncthreads();

    for (int pbase = P0; pbase < P1; pbase += 64) {
        int m = min(64, P1 - pbase);
        buf ^= 1;
        // ---- phase A ----
        for (int p = row; p < 64; p += 4) {
            if (p < m) {
                int sg = g_sseg[pbase + p];
                float4 f = g_feat[pbase + p];
                float h = f.x * w00 + f.y * w01 + f.z * w02 + f.w * w03;
                if (sg != curA) {
                    if (curA >= 0) {
                        atomicMin(&g_h0min[curA * C0 + c], encf(lmin));
                        atomicMax(&g_h0max[curA * C0 + c], encf(lmax));
                    }
                    curA = sg; lmin = h; lmax = h;
                } else {
                    lmin = fminf(lmin, h);
                    lmax = fmaxf(lmax, h);
                }
                h0s[buf][c * PAD + p] = swishf(a0 * h + c0);
                if (c == 0) ss[buf][p] = sg;
            } else {
                h0s[buf][c * PAD + p] = 0.0f;
                if (c == 0) ss[buf][p] = -1;
            }
        }
        __syncthreads();
        // ---- phase B (no trailing sync; next phase A uses other buffer) ----
        ull tssq = 0;
        float tsum = 0.0f, sssq = 0.0f;
        const int4* ss4 = (const int4*)ss[buf];
        unsigned h0base = h0base0 + (unsigned)(buf * (C0 * PAD * 4));
        for (int g4 = 0; g4 < 16; g4++) {
            int4 s = ss4[g4];
            if (s.x < 0) break;            // sorted: all-pad tail
            ull acc01 = 0, acc23 = 0;
            unsigned base = h0base + g4 * 16;
            bloop<0>(base, wp, acc01, acc23);
            float A0, A1, A2, A3;
            upk2(acc01, A0, A1);
            upk2(acc23, A2, A3);
            if (s.x == s.w) {              // uniform group (sorted)
                if (s.x != curB) {
                    if (curB >= 0) {
                        size_t ix = (size_t)curB * C1 + tid;
                        g_amin[ix] = rmin; g_amax[ix] = rmax; g_asum[ix] = rsum;
                    }
                    curB = s.x; rmin = INFINITY; rmax = -INFINITY; rsum = 0.0f;
                }
                rmin = fminf(rmin, fminf(fminf(A0, A1), fminf(A2, A3)));
                rmax = fmaxf(rmax, fmaxf(fmaxf(A0, A1), fmaxf(A2, A3)));
                float gs = (A0 + A1) + (A2 + A3);
                rsum += gs;
                tsum += gs;
                tssq = fma2(acc01, acc01, tssq);
                tssq = fma2(acc23, acc23, tssq);
            } else {
                float av[4] = {A0, A1, A2, A3};
                int sv[4] = {s.x, s.y, s.z, s.w};
#pragma unroll
                for (int k = 0; k < 4; k++) {
                    if (sv[k] < 0) continue;
                    if (sv[k] != curB) {
                        if (curB >= 0) {
                            size_t ix = (size_t)curB * C1 + tid;
                            g_amin[ix] = rmin; g_amax[ix] = rmax; g_asum[ix] = rsum;
                        }
                        curB = sv[k]; rmin = av[k]; rmax = av[k]; rsum = av[k];
                    } else {
                        rmin = fminf(rmin, av[k]);
                        rmax = fmaxf(rmax, av[k]);
                        rsum += av[k];
                    }
                    tsum += av[k];
                    sssq = fmaf(av[k], av[k], sssq);
                }
            }
        }
        float q0, q1;
        upk2(tssq, q0, q1);
        dsum += (double)tsum;
        dssq += (double)(q0 + q1 + sssq);
    }

    // final flushes
    if (curA >= 0) {
        atomicMin(&g_h0min[curA * C0 + c], encf(lmin));
        atomicMax(&g_h0max[curA * C0 + c], encf(lmax));
    }
    if (curB >= 0) {
        size_t ix = (size_t)curB * C1 + tid;
        g_amin[ix] = rmin; g_amax[ix] = rmax; g_asum[ix] = rsum;
    }
    atomicAdd(&g_s1[tid], dsum);
    atomicAdd(&g_ss1[tid], dssq);
}

// ---------------- m0 per (seg, in-channel) ----------------
__global__ void k_m0() {
    int i = blockIdx.x * blockDim.x + threadIdx.x;
    if (i >= NSEG * C0) return;
    int seg = i >> 5, ch = i & 31;
    float v = 0.0f;
    if (g_cnt[seg] > 0) {
        float mn = decf(g_h0min[i]);
        float mx = decf(g_h0max[i]);
        v = swish_seg_max(mn, mx, g_a0[ch], g_c0[ch]);
    }
    g_m0[i] = v;
}

// ---------------- finalize per segment: B, m1 endpoints, BN1 corrections ----------------
__global__ void __launch_bounds__(128)
k_fin(const float* __restrict__ W1) {
    int tid = threadIdx.x;
    float whi[32];
#pragma unroll
    for (int j = 0; j < 32; j++) whi[j] = W1[(32 + j) * C1 + tid];

    __shared__ float m0s[32];
    double dsum = 0.0, dssq = 0.0;

    for (int seg = blockIdx.x; seg < NSEG; seg += gridDim.x) {
        int cnt = g_cnt[seg];
        if (cnt == 0) continue;
        if (tid < 32) m0s[tid] = g_m0[seg * C0 + tid];
        __syncthreads();
        float B = 0.0f;
#pragma unroll
        for (int j = 0; j < 32; j++) B = fmaf(m0s[j], whi[j], B);
        size_t ix = (size_t)seg * C1 + tid;
        float amin = g_amin[ix];
        float amax = g_amax[ix];
        float as = g_asum[ix];
        g_min1[ix] = amin + B;
        g_max1[ix] = amax + B;
        float fc = (float)cnt;
        dsum += (double)(fc * B);
        dssq += (double)(2.0f * B * as + fc * B * B);
        __syncthreads();
    }
    atomicAdd(&g_s1[tid], dsum);
    atomicAdd(&g_ss1[tid], dssq);
}

// ---------------- S1: bn1 affine ----------------
__global__ void k_s1(const float* __restrict__ g1, const float* __restrict__ b1, int N) {
    int ch = threadIdx.x;
    if (ch >= C1) return;
    double dN = (double)N;
    double mu = g_s1[ch] / dN;
    double var = g_ss1[ch] / dN - mu * mu;
    double a = (double)g1[ch] / sqrt(var + (double)EPSB);
    g_a1[ch] = (float)a;
    g_c1[ch] = (float)((double)b1[ch] - mu * a);
}

// ---------------- T2: resolve m1, scatter into dense ----------------
__global__ void k_t2() {
    int i = blockIdx.x * blockDim.x + threadIdx.x;
    if (i >= NSEG * C1) return;
    int ch = i & (C1 - 1);
    int seg = i >> 7;
    float val = 0.0f;
    if (g_cnt[seg] > 0) {
        float a = g_a1[ch], c = g_c1[ch];
        float pmin = g_min1[i], pmax = g_max1[i];
        val = fmaxf(swishf(a * pmin + c), swishf(a * pmax + c));
    }
    int cy = seg % GY;
    int r = seg / GY;
    int cx = r % GX;
    int b = r / GX;
    g_dense[((b * C1 + ch) * GY + cy) * GX + cx] = val;
}

// ---------------- R: bilinear resize, float4 stores ----------------
__global__ void k_resize(float* __restrict__ out, int total) {
    int i = blockIdx.x * blockDim.x + threadIdx.x;
    if (i * 4 >= total) return;
    int xg = i % 56;
    int yo = (i / 56) % 224;
    int bc = i / (56 * 224);

    const float sy = (GY - 1.0f) / 223.0f;
    const float sx = (GX - 1.0f) / 223.0f;
    float yy = (float)yo * sy;
    int y0 = (int)floorf(yy);
    int y1 = min(y0 + 1, GY - 1);
    float wy = yy - (float)y0;

    const float* d = g_dense + (size_t)bc * GY * GX;
    const float* r0p = d + y0 * GX;
    const float* r1p = d + y1 * GX;

    float4 res;
    float* rp = (float*)&res;
#pragma unroll
    for (int s = 0; s < 4; s++) {
        int xo = xg * 4 + s;
        float xx = (float)xo * sx;
        int x0 = (int)floorf(xx);
        int x1 = min(x0 + 1, GX - 1);
        float wx = xx - (float)x0;
        float d00 = r0p[x0], d01 = r0p[x1];
        float d10 = r1p[x0], d11 = r1p[x1];
        float xh0 = d00 * (1.0f - wy) + d10 * wy;
        float xh1 = d01 * (1.0f - wy) + d11 * wy;
        rp[s] = xh0 * (1.0f - wx) + xh1 * wx;
    }
    *reinterpret_cast<float4*>(out + (size_t)i * 4) = res;
}

// ---------------- launch ----------------
extern "C" void kernel_launch(void* const* d_in, const int* in_sizes, int n_in,
                              void* d_out, int out_size) {
    const float* pts = (const float*)d_in[1];
    const float* W0  = (const float*)d_in[2];
    const float* g0  = (const float*)d_in[3];
    const float* b0  = (const float*)d_in[4];
    const float* W1  = (const float*)d_in[5];
    const float* g1  = (const float*)d_in[6];
    const float* b1  = (const float*)d_in[7];
    float* out = (float*)d_out;
    int N = in_sizes[1] / 5;
    if (N > MAXN) N = MAXN;

    k_init<<<(NSEG * C0 + 255) / 256, 256>>>();
    k_p1<<<(N + 255) / 256, 256>>>(pts, N);
    k_scan<<<1, 1024>>>();
    k_s0<<<1, 32>>>(W0, g0, b0, N);
    k_scatter<<<(N + 255) / 256, 256>>>(pts, N);
    k_seg<<<NBLK, C1>>>(W0, W1, N);
    k_m0<<<(NSEG * C0 + 255) / 256, 256>>>();
    k_fin<<<NBLK, 128>>>(W1);
    k_s1<<<1, C1>>>(g1, b1, N);
    k_t2<<<(NSEG * C1 + 255) / 256, 256>>>();
    k_resize<<<(out_size / 4 + 255) / 256, 256>>>(out, out_size);
}

// round 12
// speedup vs baseline: 1.1969x; 1.1969x over previous
#include <cuda_runtime.h>
#include <cuda_bf16.h>
#include <math.h>

// ---------------- problem constants ----------------
#define GX 116
#define GY 87
#define BATCH 4
#define NSEG (BATCH * GX * GY)          // 40368
#define MAXN 1000000
#define C0 32
#define C1 128
#define EPSB 0.001f
#define RS 36                            // h0 row stride (floats), bank-conflict-free
#define NBLK 444                         // 148 SMs x 3 blocks

typedef unsigned long long ull;

// ---------------- scratch (__device__ globals; no allocation) ----------------
__device__ int    g_inv[MAXN];
__device__ int    g_rank[MAXN];
__device__ float4 g_feat[MAXN];          // segment-sorted packed features
__device__ int    g_cnt[NSEG];
__device__ int    g_off[NSEG];
__device__ float  g_amin[NSEG * C1];     // per-seg pre-B endpoints (exclusive owner)
__device__ float  g_amax[NSEG * C1];
__device__ float  g_asum[NSEG * C1];
__device__ float  g_m0[NSEG * C0];
__device__ float  g_min1[NSEG * C1];
__device__ float  g_max1[NSEG * C1];
__device__ double g_mom[14];
__device__ double g_s1[C1];
__device__ double g_ss1[C1];
__device__ float  g_a0[C0], g_c0[C0];
__device__ float  g_a1[C1], g_c1[C1];
__device__ float  g_dense[BATCH * C1 * GY * GX];

// ---------------- helpers ----------------
__device__ __forceinline__ float swishf(float x) {
    return __fdividef(x, 1.0f + __expf(-x));
}
__device__ __forceinline__ float swish_seg_max(float pmin, float pmax, float a, float c) {
    return fmaxf(swishf(a * pmin + c), swishf(a * pmax + c));
}
__device__ __forceinline__ unsigned to_tf32(float f) {
    unsigned u;
    asm("cvt.rna.tf32.f32 %0, %1;" : "=r"(u) : "f"(f));
    return u;
}
__device__ __forceinline__ void mma_tf32(float& d0, float& d1, float& d2, float& d3,
                                         unsigned a0, unsigned a1, unsigned a2, unsigned a3,
                                         unsigned b0, unsigned b1) {
    asm volatile("mma.sync.aligned.m16n8k8.row.col.f32.tf32.tf32.f32 "
                 "{%0,%1,%2,%3}, {%4,%5,%6,%7}, {%8,%9}, {%0,%1,%2,%3};"
                 : "+f"(d0), "+f"(d1), "+f"(d2), "+f"(d3)
                 : "r"(a0), "r"(a1), "r"(a2), "r"(a3), "r"(b0), "r"(b1));
}

// ---------------- init ----------------
__global__ void k_init() {
    int i = blockIdx.x * blockDim.x + threadIdx.x;
    if (i < NSEG) g_cnt[i] = 0;
    if (i < 14)   g_mom[i] = 0.0;
    if (i < C1)   { g_s1[i] = 0.0; g_ss1[i] = 0.0; }
}

// ---------------- P1: inv, rank, histogram, feature moments ----------------
__global__ void k_p1(const float* __restrict__ pts, int N) {
    __shared__ double smom[14];
    if (threadIdx.x < 14) smom[threadIdx.x] = 0.0;
    __syncthreads();

    int i = blockIdx.x * blockDim.x + threadIdx.x;
    float m[14];
#pragma unroll
    for (int k = 0; k < 14; k++) m[k] = 0.0f;

    if (i < N) {
        const float* p = pts + (size_t)i * 5;
        float b = p[0], x = p[1], y = p[2], t = p[3], pol = p[4];
        int cx = (int)floorf(x / 3.0f);
        int cy = (int)floorf(y / 3.0f);
        int bi = (int)b;
        int inv = (bi * GX + cx) * GY + cy;
        g_inv[i] = inv;
        g_rank[i] = atomicAdd(&g_cnt[inv], 1);
        float f0 = x / 346.0f, f1 = y / 260.0f, f2 = t / 200.0f, f3 = pol;
        m[0] = f0; m[1] = f1; m[2] = f2; m[3] = f3;
        m[4] = f0 * f0; m[5] = f0 * f1; m[6] = f0 * f2; m[7] = f0 * f3;
        m[8] = f1 * f1; m[9] = f1 * f2; m[10] = f1 * f3;
        m[11] = f2 * f2; m[12] = f2 * f3; m[13] = f3 * f3;
    }

#pragma unroll
    for (int k = 0; k < 14; k++) {
#pragma unroll
        for (int off = 16; off > 0; off >>= 1)
            m[k] += __shfl_down_sync(0xFFFFFFFFu, m[k], off);
    }
    if ((threadIdx.x & 31) == 0) {
#pragma unroll
        for (int k = 0; k < 14; k++) atomicAdd(&smom[k], (double)m[k]);
    }
    __syncthreads();
    if (threadIdx.x < 14) atomicAdd(&g_mom[threadIdx.x], smom[threadIdx.x]);
}

// ---------------- scan ----------------
__global__ void k_scan() {
    __shared__ int partial[1024];
    const int PER = (NSEG + 1023) / 1024;
    int tid = threadIdx.x;
    int base = tid * PER;
    int s = 0;
    for (int k = 0; k < PER; k++) {
        int idx = base + k;
        if (idx < NSEG) s += g_cnt[idx];
    }
    partial[tid] = s;
    __syncthreads();
    for (int d = 1; d < 1024; d <<= 1) {
        int v = partial[tid];
        int add = (tid >= d) ? partial[tid - d] : 0;
        __syncthreads();
        partial[tid] = v + add;
        __syncthreads();
    }
    int run = (tid == 0) ? 0 : partial[tid - 1];
    for (int k = 0; k < PER; k++) {
        int idx = base + k;
        if (idx < NSEG) {
            g_off[idx] = run;
            run += g_cnt[idx];
        }
    }
}

// ---------------- S0: bn0 affine ----------------
__global__ void k_s0(const float* __restrict__ W0, const float* __restrict__ g0,
                     const float* __restrict__ b0, int N) {
    int ch = threadIdx.x;
    if (ch >= C0) return;
    double s0 = g_mom[0], s1 = g_mom[1], s2 = g_mom[2], s3 = g_mom[3];
    double M00 = g_mom[4], M01 = g_mom[5], M02 = g_mom[6], M03 = g_mom[7];
    double M11 = g_mom[8], M12 = g_mom[9], M13 = g_mom[10];
    double M22 = g_mom[11], M23 = g_mom[12], M33 = g_mom[13];
    double w0 = W0[ch], w1 = W0[C0 + ch], w2 = W0[2 * C0 + ch], w3 = W0[3 * C0 + ch];
    double dN = (double)N;
    double mu = (s0 * w0 + s1 * w1 + s2 * w2 + s3 * w3) / dN;
    double ex2 = (M00 * w0 * w0 + M11 * w1 * w1 + M22 * w2 * w2 + M33 * w3 * w3
                  + 2.0 * (M01 * w0 * w1 + M02 * w0 * w2 + M03 * w0 * w3
                           + M12 * w1 * w2 + M13 * w1 * w3 + M23 * w2 * w3)) / dN;
    double var = ex2 - mu * mu;
    double a = (double)g0[ch] / sqrt(var + (double)EPSB);
    g_a0[ch] = (float)a;
    g_c0[ch] = (float)((double)b0[ch] - mu * a);
}

// ---------------- scatter (no atomics) ----------------
__global__ void k_scatter(const float* __restrict__ pts, int N) {
    int i = blockIdx.x * blockDim.x + threadIdx.x;
    if (i >= N) return;
    const float* p = pts + (size_t)i * 5;
    float x = p[1], y = p[2], t = p[3], pol = p[4];
    int inv = g_inv[i];
    int pos = g_off[inv] + g_rank[i];
    g_feat[pos] = make_float4(x / 346.0f, y / 260.0f, t / 200.0f, pol);
}

// ---------------- per-segment reduction: tf32 MMA phase B ----------------
__global__ void __launch_bounds__(128, 3)
k_seg(const float* __restrict__ W0, const float* __restrict__ W1) {
    int tid  = threadIdx.x;
    int c    = tid & 31;       // phase-A channel
    int row  = tid >> 5;       // phase-A point row 0..3 (= warp id)
    int lane = tid & 31;
    int warp = tid >> 5;
    int grp  = lane >> 2;      // 0..7
    int qd   = lane & 3;       // 0..3
    int warpbase = warp * 32;  // this warp's 32 output channels

    // B fragments (tf32) for W1[:32, warp's 32 cols], held in registers
    unsigned bf[4][4][2];      // [ntile][kblk][2]
#pragma unroll
    for (int nt = 0; nt < 4; nt++) {
#pragma unroll
        for (int kb = 0; kb < 4; kb++) {
            int n = warpbase + nt * 8 + grp;
            bf[nt][kb][0] = to_tf32(W1[(kb * 8 + qd) * C1 + n]);
            bf[nt][kb][1] = to_tf32(W1[(kb * 8 + qd + 4) * C1 + n]);
        }
    }

    float w00 = W0[c], w01 = W0[C0 + c], w02 = W0[2 * C0 + c], w03 = W0[3 * C0 + c];
    float a0c = g_a0[c], c0c = g_c0[c];

    __shared__ __align__(16) float h0s[2][64 * RS];  // point-major: [pt][ch]
    __shared__ float pm[4][32], pM[4][32];

    float sumg[8], ssqg[8];     // whole-kernel partial stats, per owned channel
#pragma unroll
    for (int s = 0; s < 8; s++) { sumg[s] = 0.0f; ssqg[s] = 0.0f; }

    int buf = 0;

    for (int seg = blockIdx.x; seg < NSEG; seg += gridDim.x) {
        int cnt = g_cnt[seg];
        if (cnt == 0) continue;
        int off = g_off[seg];

        float lmin = INFINITY, lmax = -INFINITY;
        float minr[8], maxr[8], sums[8];
#pragma unroll
        for (int s = 0; s < 8; s++) { minr[s] = INFINITY; maxr[s] = -INFINITY; sums[s] = 0.0f; }

        for (int chunk = 0; chunk < cnt; chunk += 64) {
            buf ^= 1;
            int m = min(64, cnt - chunk);
            int m16 = (m + 15) & ~15;
            // ---- phase A: h0 point-major; pad rows duplicate last point ----
            for (int p = row; p < m16; p += 4) {
                int pi = min(p, m - 1);
                float4 f = g_feat[off + chunk + pi];
                float h = f.x * w00 + f.y * w01 + f.z * w02 + f.w * w03;
                lmin = fminf(lmin, h);
                lmax = fmaxf(lmax, h);
                h0s[buf][p * RS + c] = swishf(a0c * h + c0c);
            }
            __syncthreads();
            // ---- phase B: tf32 MMA; no trailing sync (double buffer) ----
            const float* hp = &h0s[buf][0];
            int nmt = m16 >> 4;
            for (int mt = 0; mt < nmt; mt++) {
                float d[4][4];
#pragma unroll
                for (int nt = 0; nt < 4; nt++) {
                    d[nt][0] = 0.0f; d[nt][1] = 0.0f; d[nt][2] = 0.0f; d[nt][3] = 0.0f;
                }
                int r0 = mt * 16 + grp;
#pragma unroll
                for (int kb = 0; kb < 4; kb++) {
                    unsigned ua0 = to_tf32(hp[r0 * RS + kb * 8 + qd]);
                    unsigned ua1 = to_tf32(hp[(r0 + 8) * RS + kb * 8 + qd]);
                    unsigned ua2 = to_tf32(hp[r0 * RS + kb * 8 + qd + 4]);
                    unsigned ua3 = to_tf32(hp[(r0 + 8) * RS + kb * 8 + qd + 4]);
#pragma unroll
                    for (int nt = 0; nt < 4; nt++)
                        mma_tf32(d[nt][0], d[nt][1], d[nt][2], d[nt][3],
                                 ua0, ua1, ua2, ua3, bf[nt][kb][0], bf[nt][kb][1]);
                }
                bool v0 = r0 < m;
                bool v1 = (r0 + 8) < m;
#pragma unroll
                for (int nt = 0; nt < 4; nt++) {
#pragma unroll
                    for (int j = 0; j < 2; j++) {
                        int s = nt * 2 + j;
                        float x0 = d[nt][j];       // row r0
                        float x1 = d[nt][2 + j];   // row r0+8
                        minr[s] = fminf(minr[s], fminf(x0, x1));
                        maxr[s] = fmaxf(maxr[s], fmaxf(x0, x1));
                        if (v0) { sums[s] += x0; ssqg[s] = fmaf(x0, x0, ssqg[s]); }
                        if (v1) { sums[s] += x1; ssqg[s] = fmaf(x1, x1, ssqg[s]); }
                    }
                }
            }
        }

        // ---- phase-A m0 (needs all rows' ranges) ----
        pm[row][c] = lmin;
        pM[row][c] = lmax;
        __syncthreads();
        if (tid < 32) {
            float mn = fminf(fminf(pm[0][tid], pm[1][tid]), fminf(pm[2][tid], pm[3][tid]));
            float mx = fmaxf(fmaxf(pM[0][tid], pM[1][tid]), fmaxf(pM[2][tid], pM[3][tid]));
            g_m0[seg * C0 + tid] = swish_seg_max(mn, mx, g_a0[tid], g_c0[tid]);
        }

        // accumulate PARTIAL sums into whole-kernel stats BEFORE cross-thread reduce
#pragma unroll
        for (int s = 0; s < 8; s++) sumg[s] += sums[s];

        // ---- reduce stats across the 8 row-threads (xor 4,8,16) ----
#pragma unroll
        for (int s = 0; s < 8; s++) {
#pragma unroll
            for (int dd = 4; dd <= 16; dd <<= 1) {
                minr[s] = fminf(minr[s], __shfl_xor_sync(0xFFFFFFFFu, minr[s], dd));
                maxr[s] = fmaxf(maxr[s], __shfl_xor_sync(0xFFFFFFFFu, maxr[s], dd));
                sums[s] += __shfl_xor_sync(0xFFFFFFFFu, sums[s], dd);
            }
        }
        if (grp == 0) {
#pragma unroll
            for (int s = 0; s < 8; s++) {
                int ch = warpbase + (s >> 1) * 8 + 2 * qd + (s & 1);
                size_t ix = (size_t)seg * C1 + ch;
                g_amin[ix] = minr[s];
                g_amax[ix] = maxr[s];
                g_asum[ix] = sums[s];
            }
        }
        __syncthreads();
    }

    // ---- final: reduce whole-kernel stats and flush ----
#pragma unroll
    for (int s = 0; s < 8; s++) {
#pragma unroll
        for (int dd = 4; dd <= 16; dd <<= 1) {
            sumg[s] += __shfl_xor_sync(0xFFFFFFFFu, sumg[s], dd);
            ssqg[s] += __shfl_xor_sync(0xFFFFFFFFu, ssqg[s], dd);
        }
        if (grp == 0) {
            int ch = warpbase + (s >> 1) * 8 + 2 * qd + (s & 1);
            atomicAdd(&g_s1[ch], (double)sumg[s]);
            atomicAdd(&g_ss1[ch], (double)ssqg[s]);
        }
    }
}

// ---------------- finalize per segment: B, m1 endpoints, BN1 corrections ----------------
__global__ void __launch_bounds__(128)
k_fin(const float* __restrict__ W1) {
    int tid = threadIdx.x;
    float whi[32];
#pragma unroll
    for (int j = 0; j < 32; j++) whi[j] = W1[(32 + j) * C1 + tid];

    __shared__ float m0s[32];
    double dsum = 0.0, dssq = 0.0;

    for (int seg = blockIdx.x; seg < NSEG; seg += gridDim.x) {
        int cnt = g_cnt[seg];
        if (cnt == 0) continue;
        if (tid < 32) m0s[tid] = g_m0[seg * C0 + tid];
        __syncthreads();
        float B = 0.0f;
#pragma unroll
        for (int j = 0; j < 32; j++) B = fmaf(m0s[j], whi[j], B);
        size_t ix = (size_t)seg * C1 + tid;
        float amin = g_amin[ix];
        float amax = g_amax[ix];
        float as = g_asum[ix];
        g_min1[ix] = amin + B;
        g_max1[ix] = amax + B;
        float fc = (float)cnt;
        dsum += (double)(fc * B);
        dssq += (double)(2.0f * B * as + fc * B * B);
        __syncthreads();
    }
    atomicAdd(&g_s1[tid], dsum);
    atomicAdd(&g_ss1[tid], dssq);
}

// ---------------- S1: bn1 affine ----------------
__global__ void k_s1(const float* __restrict__ g1, const float* __restrict__ b1, int N) {
    int ch = threadIdx.x;
    if (ch >= C1) return;
    double dN = (double)N;
    double mu = g_s1[ch] / dN;
    double var = g_ss1[ch] / dN - mu * mu;
    double a = (double)g1[ch] / sqrt(var + (double)EPSB);
    g_a1[ch] = (float)a;
    g_c1[ch] = (float)((double)b1[ch] - mu * a);
}

// ---------------- T2: resolve m1, scatter into dense ----------------
__global__ void k_t2() {
    int i = blockIdx.x * blockDim.x + threadIdx.x;
    if (i >= NSEG * C1) return;
    int ch = i & (C1 - 1);
    int seg = i >> 7;
    float val = 0.0f;
    if (g_cnt[seg] > 0) {
        float a = g_a1[ch], c = g_c1[ch];
        float pmin = g_min1[i], pmax = g_max1[i];
        val = fmaxf(swishf(a * pmin + c), swishf(a * pmax + c));
    }
    int cy = seg % GY;
    int r = seg / GY;
    int cx = r % GX;
    int b = r / GX;
    g_dense[((b * C1 + ch) * GY + cy) * GX + cx] = val;
}

// ---------------- R: bilinear resize, float4 stores ----------------
__global__ void k_resize(float* __restrict__ out, int total) {
    int i = blockIdx.x * blockDim.x + threadIdx.x;
    if (i * 4 >= total) return;
    int xg = i % 56;
    int yo = (i / 56) % 224;
    int bc = i / (56 * 224);

    const float sy = (GY - 1.0f) / 223.0f;
    const float sx = (GX - 1.0f) / 223.0f;
    float yy = (float)yo * sy;
    int y0 = (int)floorf(yy);
    int y1 = min(y0 + 1, GY - 1);
    float wy = yy - (float)y0;

    const float* d = g_dense + (size_t)bc * GY * GX;
    const float* r0p = d + y0 * GX;
    const float* r1p = d + y1 * GX;

    float4 res;
    float* rp = (float*)&res;
#pragma unroll
    for (int s = 0; s < 4; s++) {
        int xo = xg * 4 + s;
        float xx = (float)xo * sx;
        int x0 = (int)floorf(xx);
        int x1 = min(x0 + 1, GX - 1);
        float wx = xx - (float)x0;
        float d00 = r0p[x0], d01 = r0p[x1];
        float d10 = r1p[x0], d11 = r1p[x1];
        float xh0 = d00 * (1.0f - wy) + d10 * wy;
        float xh1 = d01 * (1.0f - wy) + d11 * wy;
        rp[s] = xh0 * (1.0f - wx) + xh1 * wx;
    }
    *reinterpret_cast<float4*>(out + (size_t)i * 4) = res;
}

// ---------------- launch ----------------
extern "C" void kernel_launch(void* const* d_in, const int* in_sizes, int n_in,
                              void* d_out, int out_size) {
    const float* pts = (const float*)d_in[1];
    const float* W0  = (const float*)d_in[2];
    const float* g0  = (const float*)d_in[3];
    const float* b0  = (const float*)d_in[4];
    const float* W1  = (const float*)d_in[5];
    const float* g1  = (const float*)d_in[6];
    const float* b1  = (const float*)d_in[7];
    float* out = (float*)d_out;
    int N = in_sizes[1] / 5;
    if (N > MAXN) N = MAXN;

    k_init<<<(NSEG + 255) / 256, 256>>>();
    k_p1<<<(N + 255) / 256, 256>>>(pts, N);
    k_scan<<<1, 1024>>>();
    k_s0<<<1, 32>>>(W0, g0, b0, N);
    k_scatter<<<(N + 255) / 256, 256>>>(pts, N);
    k_seg<<<NBLK, 128>>>(W0, W1);
    k_fin<<<NBLK, 128>>>(W1);
    k_s1<<<1, C1>>>(g1, b1, N);
    k_t2<<<(NSEG * C1 + 255) / 256, 256>>>();
    k_resize<<<(out_size / 4 + 255) / 256, 256>>>(out, out_size);
}

// round 14
// speedup vs baseline: 1.3397x; 1.1193x over previous
#include <cuda_runtime.h>
#include <cuda_bf16.h>
#include <math.h>

// ---------------- problem constants ----------------
#define GX 116
#define GY 87
#define BATCH 4
#define NSEG (BATCH * GX * GY)          // 40368
#define MAXN 1000000
#define C0 32
#define C1 128
#define EPSB 0.001f
#define RS 36                            // h0 row stride (floats), bank-conflict-free
#define NBLK 592                         // 148 SMs x 4 blocks

typedef unsigned long long ull;

// ---------------- scratch (__device__ globals; no allocation) ----------------
__device__ int    g_inv[MAXN];
__device__ int    g_rank[MAXN];
__device__ float4 g_feat[MAXN];          // segment-sorted packed features
__device__ int    g_cnt[NSEG];
__device__ int    g_off[NSEG];
__device__ float  g_amin[NSEG * C1];     // per-seg pre-B endpoints (exclusive owner)
__device__ float  g_amax[NSEG * C1];
__device__ float  g_asum[NSEG * C1];
__device__ float  g_m0[NSEG * C0];
__device__ float  g_min1[NSEG * C1];
__device__ float  g_max1[NSEG * C1];
__device__ double g_mom[14];
__device__ double g_s1[C1];
__device__ double g_ss1[C1];
__device__ float  g_a0[C0], g_c0[C0];
__device__ float  g_a1[C1], g_c1[C1];
__device__ float  g_dense[BATCH * C1 * GY * GX];

// ---------------- helpers ----------------
__device__ __forceinline__ float swishf(float x) {
    return __fdividef(x, 1.0f + __expf(-x));
}
__device__ __forceinline__ float swish_seg_max(float pmin, float pmax, float a, float c) {
    return fmaxf(swishf(a * pmin + c), swishf(a * pmax + c));
}
__device__ __forceinline__ unsigned to_tf32(float f) {
    unsigned u;
    asm("cvt.rna.tf32.f32 %0, %1;" : "=r"(u) : "f"(f));
    return u;
}
__device__ __forceinline__ void mma_tf32(float& d0, float& d1, float& d2, float& d3,
                                         unsigned a0, unsigned a1, unsigned a2, unsigned a3,
                                         unsigned b0, unsigned b1) {
    asm volatile("mma.sync.aligned.m16n8k8.row.col.f32.tf32.tf32.f32 "
                 "{%0,%1,%2,%3}, {%4,%5,%6,%7}, {%8,%9}, {%0,%1,%2,%3};"
                 : "+f"(d0), "+f"(d1), "+f"(d2), "+f"(d3)
                 : "r"(a0), "r"(a1), "r"(a2), "r"(a3), "r"(b0), "r"(b1));
}
__device__ __forceinline__ void pfL2(const void* p) {
    asm volatile("prefetch.global.L2 [%0];" :: "l"(p));
}

// ---------------- init ----------------
__global__ void k_init() {
    int i = blockIdx.x * blockDim.x + threadIdx.x;
    if (i < NSEG) g_cnt[i] = 0;
    if (i < 14)   g_mom[i] = 0.0;
    if (i < C1)   { g_s1[i] = 0.0; g_ss1[i] = 0.0; }
}

// ---------------- P1: inv, rank, histogram, feature moments ----------------
__global__ void k_p1(const float* __restrict__ pts, int N) {
    __shared__ double smom[14];
    if (threadIdx.x < 14) smom[threadIdx.x] = 0.0;
    __syncthreads();

    int i = blockIdx.x * blockDim.x + threadIdx.x;
    float m[14];
#pragma unroll
    for (int k = 0; k < 14; k++) m[k] = 0.0f;

    if (i < N) {
        const float* p = pts + (size_t)i * 5;
        float b = p[0], x = p[1], y = p[2], t = p[3], pol = p[4];
        int cx = (int)floorf(x / 3.0f);
        int cy = (int)floorf(y / 3.0f);
        int bi = (int)b;
        int inv = (bi * GX + cx) * GY + cy;
        g_inv[i] = inv;
        g_rank[i] = atomicAdd(&g_cnt[inv], 1);
        float f0 = x / 346.0f, f1 = y / 260.0f, f2 = t / 200.0f, f3 = pol;
        m[0] = f0; m[1] = f1; m[2] = f2; m[3] = f3;
        m[4] = f0 * f0; m[5] = f0 * f1; m[6] = f0 * f2; m[7] = f0 * f3;
        m[8] = f1 * f1; m[9] = f1 * f2; m[10] = f1 * f3;
        m[11] = f2 * f2; m[12] = f2 * f3; m[13] = f3 * f3;
    }

#pragma unroll
    for (int k = 0; k < 14; k++) {
#pragma unroll
        for (int off = 16; off > 0; off >>= 1)
            m[k] += __shfl_down_sync(0xFFFFFFFFu, m[k], off);
    }
    if ((threadIdx.x & 31) == 0) {
#pragma unroll
        for (int k = 0; k < 14; k++) atomicAdd(&smom[k], (double)m[k]);
    }
    __syncthreads();
    if (threadIdx.x < 14) atomicAdd(&g_mom[threadIdx.x], smom[threadIdx.x]);
}

// ---------------- scan ----------------
__global__ void k_scan() {
    __shared__ int partial[1024];
    const int PER = (NSEG + 1023) / 1024;
    int tid = threadIdx.x;
    int base = tid * PER;
    int s = 0;
    for (int k = 0; k < PER; k++) {
        int idx = base + k;
        if (idx < NSEG) s += g_cnt[idx];
    }
    partial[tid] = s;
    __syncthreads();
    for (int d = 1; d < 1024; d <<= 1) {
        int v = partial[tid];
        int add = (tid >= d) ? partial[tid - d] : 0;
        __syncthreads();
        partial[tid] = v + add;
        __syncthreads();
    }
    int run = (tid == 0) ? 0 : partial[tid - 1];
    for (int k = 0; k < PER; k++) {
        int idx = base + k;
        if (idx < NSEG) {
            g_off[idx] = run;
            run += g_cnt[idx];
        }
    }
}

// ---------------- S0: bn0 affine ----------------
__global__ void k_s0(const float* __restrict__ W0, const float* __restrict__ g0,
                     const float* __restrict__ b0, int N) {
    int ch = threadIdx.x;
    if (ch >= C0) return;
    double s0 = g_mom[0], s1 = g_mom[1], s2 = g_mom[2], s3 = g_mom[3];
    double M00 = g_mom[4], M01 = g_mom[5], M02 = g_mom[6], M03 = g_mom[7];
    double M11 = g_mom[8], M12 = g_mom[9], M13 = g_mom[10];
    double M22 = g_mom[11], M23 = g_mom[12], M33 = g_mom[13];
    double w0 = W0[ch], w1 = W0[C0 + ch], w2 = W0[2 * C0 + ch], w3 = W0[3 * C0 + ch];
    double dN = (double)N;
    double mu = (s0 * w0 + s1 * w1 + s2 * w2 + s3 * w3) / dN;
    double ex2 = (M00 * w0 * w0 + M11 * w1 * w1 + M22 * w2 * w2 + M33 * w3 * w3
                  + 2.0 * (M01 * w0 * w1 + M02 * w0 * w2 + M03 * w0 * w3
                           + M12 * w1 * w2 + M13 * w1 * w3 + M23 * w2 * w3)) / dN;
    double var = ex2 - mu * mu;
    double a = (double)g0[ch] / sqrt(var + (double)EPSB);
    g_a0[ch] = (float)a;
    g_c0[ch] = (float)((double)b0[ch] - mu * a);
}

// ---------------- scatter (no atomics) ----------------
__global__ void k_scatter(const float* __restrict__ pts, int N) {
    int i = blockIdx.x * blockDim.x + threadIdx.x;
    if (i >= N) return;
    const float* p = pts + (size_t)i * 5;
    float x = p[1], y = p[2], t = p[3], pol = p[4];
    int inv = g_inv[i];
    int pos = g_off[inv] + g_rank[i];
    g_feat[pos] = make_float4(x / 346.0f, y / 260.0f, t / 200.0f, pol);
}

// ---------------- per-segment reduction: tf32 MMA phase B ----------------
__global__ void __launch_bounds__(128, 4)
k_seg(const float* __restrict__ W0, const float* __restrict__ W1) {
    int tid  = threadIdx.x;
    int c    = tid & 31;       // phase-A channel
    int row  = tid >> 5;       // phase-A point row 0..3 (= warp id)
    int lane = tid & 31;
    int warp = tid >> 5;
    int grp  = lane >> 2;      // 0..7
    int qd   = lane & 3;       // 0..3
    int warpbase = warp * 32;  // this warp's 32 output channels

    // B fragments (tf32) for W1[:32, warp's 32 cols], held in registers
    unsigned bf[4][4][2];      // [ntile][kblk][2]
#pragma unroll
    for (int nt = 0; nt < 4; nt++) {
#pragma unroll
        for (int kb = 0; kb < 4; kb++) {
            int n = warpbase + nt * 8 + grp;
            bf[nt][kb][0] = to_tf32(W1[(kb * 8 + qd) * C1 + n]);
            bf[nt][kb][1] = to_tf32(W1[(kb * 8 + qd + 4) * C1 + n]);
        }
    }

    float w00 = W0[c], w01 = W0[C0 + c], w02 = W0[2 * C0 + c], w03 = W0[3 * C0 + c];
    float a0c = g_a0[c], c0c = g_c0[c];

    __shared__ __align__(16) float h0s[2][64 * RS];  // point-major: [pt][ch]
    __shared__ float pm[4][32], pM[4][32];

    float sumg[8], ssqg[8];     // whole-kernel partial stats, per owned channel
#pragma unroll
    for (int s = 0; s < 8; s++) { sumg[s] = 0.0f; ssqg[s] = 0.0f; }

    int buf = 0;

    for (int seg = blockIdx.x; seg < NSEG; seg += gridDim.x) {
        int cnt = g_cnt[seg];
        if (cnt == 0) continue;
        int off = g_off[seg];

        // prefetch next owned segment's first 64 points into L2 (overlaps this segment)
        {
            int nseg = seg + gridDim.x;
            if (nseg < NSEG && tid < 8) {
                int ncnt = g_cnt[nseg];
                if (tid * 8 < ncnt) pfL2(&g_feat[g_off[nseg] + tid * 8]);
            }
        }

        float lmin = INFINITY, lmax = -INFINITY;
        float minr[8], maxr[8], sums[8];
#pragma unroll
        for (int s = 0; s < 8; s++) { minr[s] = INFINITY; maxr[s] = -INFINITY; sums[s] = 0.0f; }

        for (int chunk = 0; chunk < cnt; chunk += 64) {
            buf ^= 1;
            int m = min(64, cnt - chunk);
            int m16 = (m + 15) & ~15;
            // ---- phase A: h0 point-major; pad rows duplicate last point ----
            for (int p = row; p < m16; p += 4) {
                int pi = min(p, m - 1);
                float4 f = g_feat[off + chunk + pi];
                float h = f.x * w00 + f.y * w01 + f.z * w02 + f.w * w03;
                lmin = fminf(lmin, h);
                lmax = fmaxf(lmax, h);
                h0s[buf][p * RS + c] = swishf(a0c * h + c0c);
            }
            __syncthreads();
            // ---- phase B: tf32 MMA; no trailing sync (double buffer) ----
            const float* hp = &h0s[buf][0];
            int nmt = m16 >> 4;
            for (int mt = 0; mt < nmt; mt++) {
                float d[4][4];
#pragma unroll
                for (int nt = 0; nt < 4; nt++) {
                    d[nt][0] = 0.0f; d[nt][1] = 0.0f; d[nt][2] = 0.0f; d[nt][3] = 0.0f;
                }
                int r0 = mt * 16 + grp;
#pragma unroll
                for (int kb = 0; kb < 4; kb++) {
                    unsigned ua0 = to_tf32(hp[r0 * RS + kb * 8 + qd]);
                    unsigned ua1 = to_tf32(hp[(r0 + 8) * RS + kb * 8 + qd]);
                    unsigned ua2 = to_tf32(hp[r0 * RS + kb * 8 + qd + 4]);
                    unsigned ua3 = to_tf32(hp[(r0 + 8) * RS + kb * 8 + qd + 4]);
#pragma unroll
                    for (int nt = 0; nt < 4; nt++)
                        mma_tf32(d[nt][0], d[nt][1], d[nt][2], d[nt][3],
                                 ua0, ua1, ua2, ua3, bf[nt][kb][0], bf[nt][kb][1]);
                }
                bool v0 = r0 < m;
                bool v1 = (r0 + 8) < m;
#pragma unroll
                for (int nt = 0; nt < 4; nt++) {
#pragma unroll
                    for (int j = 0; j < 2; j++) {
                        int s = nt * 2 + j;
                        float x0 = d[nt][j];       // row r0
                        float x1 = d[nt][2 + j];   // row r0+8
                        minr[s] = fminf(minr[s], fminf(x0, x1));
                        maxr[s] = fmaxf(maxr[s], fmaxf(x0, x1));
                        if (v0) { sums[s] += x0; ssqg[s] = fmaf(x0, x0, ssqg[s]); }
                        if (v1) { sums[s] += x1; ssqg[s] = fmaf(x1, x1, ssqg[s]); }
                    }
                }
            }
        }

        // ---- phase-A m0 (needs all rows' ranges) ----
        pm[row][c] = lmin;
        pM[row][c] = lmax;
        __syncthreads();
        if (tid < 32) {
            float mn = fminf(fminf(pm[0][tid], pm[1][tid]), fminf(pm[2][tid], pm[3][tid]));
            float mx = fmaxf(fmaxf(pM[0][tid], pM[1][tid]), fmaxf(pM[2][tid], pM[3][tid]));
            g_m0[seg * C0 + tid] = swish_seg_max(mn, mx, g_a0[tid], g_c0[tid]);
        }

        // accumulate PARTIAL sums into whole-kernel stats BEFORE cross-thread reduce
#pragma unroll
        for (int s = 0; s < 8; s++) sumg[s] += sums[s];

        // ---- reduce stats across the 8 row-threads (xor 4,8,16) ----
#pragma unroll
        for (int s = 0; s < 8; s++) {
#pragma unroll
            for (int dd = 4; dd <= 16; dd <<= 1) {
                minr[s] = fminf(minr[s], __shfl_xor_sync(0xFFFFFFFFu, minr[s], dd));
                maxr[s] = fmaxf(maxr[s], __shfl_xor_sync(0xFFFFFFFFu, maxr[s], dd));
                sums[s] += __shfl_xor_sync(0xFFFFFFFFu, sums[s], dd);
            }
        }
        if (grp == 0) {
#pragma unroll
            for (int s = 0; s < 8; s++) {
                int ch = warpbase + (s >> 1) * 8 + 2 * qd + (s & 1);
                size_t ix = (size_t)seg * C1 + ch;
                g_amin[ix] = minr[s];
                g_amax[ix] = maxr[s];
                g_asum[ix] = sums[s];
            }
        }
        __syncthreads();
    }

    // ---- final: reduce whole-kernel stats and flush ----
#pragma unroll
    for (int s = 0; s < 8; s++) {
#pragma unroll
        for (int dd = 4; dd <= 16; dd <<= 1) {
            sumg[s] += __shfl_xor_sync(0xFFFFFFFFu, sumg[s], dd);
            ssqg[s] += __shfl_xor_sync(0xFFFFFFFFu, ssqg[s], dd);
        }
        if (grp == 0) {
            int ch = warpbase + (s >> 1) * 8 + 2 * qd + (s & 1);
            atomicAdd(&g_s1[ch], (double)sumg[s]);
            atomicAdd(&g_ss1[ch], (double)ssqg[s]);
        }
    }
}

// ---------------- finalize per segment: B, m1 endpoints, BN1 corrections ----------------
__global__ void __launch_bounds__(128)
k_fin(const float* __restrict__ W1) {
    int tid = threadIdx.x;
    float whi[32];
#pragma unroll
    for (int j = 0; j < 32; j++) whi[j] = W1[(32 + j) * C1 + tid];

    __shared__ float m0s[32];
    double dsum = 0.0, dssq = 0.0;

    for (int seg = blockIdx.x; seg < NSEG; seg += gridDim.x) {
        int cnt = g_cnt[seg];
        if (cnt == 0) continue;
        if (tid < 32) m0s[tid] = g_m0[seg * C0 + tid];
        __syncthreads();
        float B = 0.0f;
#pragma unroll
        for (int j = 0; j < 32; j++) B = fmaf(m0s[j], whi[j], B);
        size_t ix = (size_t)seg * C1 + tid;
        float amin = g_amin[ix];
        float amax = g_amax[ix];
        float as = g_asum[ix];
        g_min1[ix] = amin + B;
        g_max1[ix] = amax + B;
        float fc = (float)cnt;
        dsum += (double)(fc * B);
        dssq += (double)(2.0f * B * as + fc * B * B);
        __syncthreads();
    }
    atomicAdd(&g_s1[tid], dsum);
    atomicAdd(&g_ss1[tid], dssq);
}

// ---------------- S1: bn1 affine ----------------
__global__ void k_s1(const float* __restrict__ g1, const float* __restrict__ b1, int N) {
    int ch = threadIdx.x;
    if (ch >= C1) return;
    double dN = (double)N;
    double mu = g_s1[ch] / dN;
    double var = g_ss1[ch] / dN - mu * mu;
    double a = (double)g1[ch] / sqrt(var + (double)EPSB);
    g_a1[ch] = (float)a;
    g_c1[ch] = (float)((double)b1[ch] - mu * a);
}

// ---------------- T2: resolve m1, scatter into dense ----------------
__global__ void k_t2() {
    int i = blockIdx.x * blockDim.x + threadIdx.x;
    if (i >= NSEG * C1) return;
    int ch = i & (C1 - 1);
    int seg = i >> 7;
    float val = 0.0f;
    if (g_cnt[seg] > 0) {
        float a = g_a1[ch], c = g_c1[ch];
        float pmin = g_min1[i], pmax = g_max1[i];
        val = fmaxf(swishf(a * pmin + c), swishf(a * pmax + c));
    }
    int cy = seg % GY;
    int r = seg / GY;
    int cx = r % GX;
    int b = r / GX;
    g_dense[((b * C1 + ch) * GY + cy) * GX + cx] = val;
}

// ---------------- R: bilinear resize, float4 stores ----------------
__global__ void k_resize(float* __restrict__ out, int total) {
    int i = blockIdx.x * blockDim.x + threadIdx.x;
    if (i * 4 >= total) return;
    int xg = i % 56;
    int yo = (i / 56) % 224;
    int bc = i / (56 * 224);

    const float sy = (GY - 1.0f) / 223.0f;
    const float sx = (GX - 1.0f) / 223.0f;
    float yy = (float)yo * sy;
    int y0 = (int)floorf(yy);
    int y1 = min(y0 + 1, GY - 1);
    float wy = yy - (float)y0;

    const float* d = g_dense + (size_t)bc * GY * GX;
    const float* r0p = d + y0 * GX;
    const float* r1p = d + y1 * GX;

    float4 res;
    float* rp = (float*)&res;
#pragma unroll
    for (int s = 0; s < 4; s++) {
        int xo = xg * 4 + s;
        float xx = (float)xo * sx;
        int x0 = (int)floorf(xx);
        int x1 = min(x0 + 1, GX - 1);
        float wx = xx - (float)x0;
        float d00 = r0p[x0], d01 = r0p[x1];
        float d10 = r1p[x0], d11 = r1p[x1];
        float xh0 = d00 * (1.0f - wy) + d10 * wy;
        float xh1 = d01 * (1.0f - wy) + d11 * wy;
        rp[s] = xh0 * (1.0f - wx) + xh1 * wx;
    }
    *reinterpret_cast<float4*>(out + (size_t)i * 4) = res;
}

// ---------------- launch ----------------
extern "C" void kernel_launch(void* const* d_in, const int* in_sizes, int n_in,
                              void* d_out, int out_size) {
    const float* pts = (const float*)d_in[1];
    const float* W0  = (const float*)d_in[2];
    const float* g0  = (const float*)d_in[3];
    const float* b0  = (const float*)d_in[4];
    const float* W1  = (const float*)d_in[5];
    const float* g1  = (const float*)d_in[6];
    const float* b1  = (const float*)d_in[7];
    float* out = (float*)d_out;
    int N = in_sizes[1] / 5;
    if (N > MAXN) N = MAXN;

    k_init<<<(NSEG + 255) / 256, 256>>>();
    k_p1<<<(N + 255) / 256, 256>>>(pts, N);
    k_scan<<<1, 1024>>>();
    k_s0<<<1, 32>>>(W0, g0, b0, N);
    k_scatter<<<(N + 255) / 256, 256>>>(pts, N);
    k_seg<<<NBLK, 128>>>(W0, W1);
    k_fin<<<NBLK, 128>>>(W1);
    k_s1<<<1, C1>>>(g1, b1, N);
    k_t2<<<(NSEG * C1 + 255) / 256, 256>>>();
    k_resize<<<(out_size / 4 + 255) / 256, 256>>>(out, out_size);
}

// round 15
// speedup vs baseline: 1.4132x; 1.0549x over previous
#include <cuda_runtime.h>
#include <cuda_bf16.h>
#include <math.h>

// ---------------- problem constants ----------------
#define GX 116
#define GY 87
#define BATCH 4
#define NSEG (BATCH * GX * GY)          // 40368
#define MAXN 1000000
#define C0 32
#define C1 128
#define EPSB 0.001f
#define RS 36                            // h0 row stride (floats), bank-conflict-free
#define NBLK 592                         // 148 SMs x 4 blocks

typedef unsigned long long ull;

// ---------------- scratch (__device__ globals; no allocation) ----------------
__device__ int    g_inv[MAXN];
__device__ int    g_rank[MAXN];
__device__ float4 g_feat[MAXN];          // segment-sorted packed features
__device__ int    g_cnt[NSEG];
__device__ int    g_off[NSEG];
__device__ float  g_amin[NSEG * C1];     // per-seg pre-B endpoints (exclusive owner)
__device__ float  g_amax[NSEG * C1];
__device__ float  g_m0[NSEG * C0];
__device__ float  g_sh0[NSEG * C0];      // per-seg sum of h0 (for Σa via linearity)
__device__ float  g_min1[NSEG * C1];
__device__ float  g_max1[NSEG * C1];
__device__ double g_mom[14];
__device__ double g_s1[C1];
__device__ double g_ss1[C1];
__device__ float  g_a0[C0], g_c0[C0];
__device__ float  g_a1[C1], g_c1[C1];
__device__ float  g_dense[BATCH * C1 * GY * GX];

// ---------------- helpers ----------------
__device__ __forceinline__ float swishf(float x) {
    return __fdividef(x, 1.0f + __expf(-x));
}
__device__ __forceinline__ float swish_seg_max(float pmin, float pmax, float a, float c) {
    return fmaxf(swishf(a * pmin + c), swishf(a * pmax + c));
}
__device__ __forceinline__ unsigned to_tf32(float f) {
    unsigned u;
    asm("cvt.rna.tf32.f32 %0, %1;" : "=r"(u) : "f"(f));
    return u;
}
__device__ __forceinline__ void mma_tf32(float& d0, float& d1, float& d2, float& d3,
                                         unsigned a0, unsigned a1, unsigned a2, unsigned a3,
                                         unsigned b0, unsigned b1) {
    asm volatile("mma.sync.aligned.m16n8k8.row.col.f32.tf32.tf32.f32 "
                 "{%0,%1,%2,%3}, {%4,%5,%6,%7}, {%8,%9}, {%0,%1,%2,%3};"
                 : "+f"(d0), "+f"(d1), "+f"(d2), "+f"(d3)
                 : "r"(a0), "r"(a1), "r"(a2), "r"(a3), "r"(b0), "r"(b1));
}
__device__ __forceinline__ void pfL2(const void* p) {
    asm volatile("prefetch.global.L2 [%0];" :: "l"(p));
}

// ---------------- init ----------------
__global__ void k_init() {
    int i = blockIdx.x * blockDim.x + threadIdx.x;
    if (i < NSEG) g_cnt[i] = 0;
    if (i < 14)   g_mom[i] = 0.0;
    if (i < C1)   { g_s1[i] = 0.0; g_ss1[i] = 0.0; }
}

// ---------------- P1: inv, rank, histogram, feature moments ----------------
__global__ void k_p1(const float* __restrict__ pts, int N) {
    __shared__ double smom[14];
    if (threadIdx.x < 14) smom[threadIdx.x] = 0.0;
    __syncthreads();

    int i = blockIdx.x * blockDim.x + threadIdx.x;
    float m[14];
#pragma unroll
    for (int k = 0; k < 14; k++) m[k] = 0.0f;

    if (i < N) {
        const float* p = pts + (size_t)i * 5;
        float b = p[0], x = p[1], y = p[2], t = p[3], pol = p[4];
        int cx = (int)floorf(x / 3.0f);
        int cy = (int)floorf(y / 3.0f);
        int bi = (int)b;
        int inv = (bi * GX + cx) * GY + cy;
        g_inv[i] = inv;
        g_rank[i] = atomicAdd(&g_cnt[inv], 1);
        float f0 = x / 346.0f, f1 = y / 260.0f, f2 = t / 200.0f, f3 = pol;
        m[0] = f0; m[1] = f1; m[2] = f2; m[3] = f3;
        m[4] = f0 * f0; m[5] = f0 * f1; m[6] = f0 * f2; m[7] = f0 * f3;
        m[8] = f1 * f1; m[9] = f1 * f2; m[10] = f1 * f3;
        m[11] = f2 * f2; m[12] = f2 * f3; m[13] = f3 * f3;
    }

#pragma unroll
    for (int k = 0; k < 14; k++) {
#pragma unroll
        for (int off = 16; off > 0; off >>= 1)
            m[k] += __shfl_down_sync(0xFFFFFFFFu, m[k], off);
    }
    if ((threadIdx.x & 31) == 0) {
#pragma unroll
        for (int k = 0; k < 14; k++) atomicAdd(&smom[k], (double)m[k]);
    }
    __syncthreads();
    if (threadIdx.x < 14) atomicAdd(&g_mom[threadIdx.x], smom[threadIdx.x]);
}

// ---------------- scan ----------------
__global__ void k_scan() {
    __shared__ int partial[1024];
    const int PER = (NSEG + 1023) / 1024;
    int tid = threadIdx.x;
    int base = tid * PER;
    int s = 0;
    for (int k = 0; k < PER; k++) {
        int idx = base + k;
        if (idx < NSEG) s += g_cnt[idx];
    }
    partial[tid] = s;
    __syncthreads();
    for (int d = 1; d < 1024; d <<= 1) {
        int v = partial[tid];
        int add = (tid >= d) ? partial[tid - d] : 0;
        __syncthreads();
        partial[tid] = v + add;
        __syncthreads();
    }
    int run = (tid == 0) ? 0 : partial[tid - 1];
    for (int k = 0; k < PER; k++) {
        int idx = base + k;
        if (idx < NSEG) {
            g_off[idx] = run;
            run += g_cnt[idx];
        }
    }
}

// ---------------- S0: bn0 affine ----------------
__global__ void k_s0(const float* __restrict__ W0, const float* __restrict__ g0,
                     const float* __restrict__ b0, int N) {
    int ch = threadIdx.x;
    if (ch >= C0) return;
    double s0 = g_mom[0], s1 = g_mom[1], s2 = g_mom[2], s3 = g_mom[3];
    double M00 = g_mom[4], M01 = g_mom[5], M02 = g_mom[6], M03 = g_mom[7];
    double M11 = g_mom[8], M12 = g_mom[9], M13 = g_mom[10];
    double M22 = g_mom[11], M23 = g_mom[12], M33 = g_mom[13];
    double w0 = W0[ch], w1 = W0[C0 + ch], w2 = W0[2 * C0 + ch], w3 = W0[3 * C0 + ch];
    double dN = (double)N;
    double mu = (s0 * w0 + s1 * w1 + s2 * w2 + s3 * w3) / dN;
    double ex2 = (M00 * w0 * w0 + M11 * w1 * w1 + M22 * w2 * w2 + M33 * w3 * w3
                  + 2.0 * (M01 * w0 * w1 + M02 * w0 * w2 + M03 * w0 * w3
                           + M12 * w1 * w2 + M13 * w1 * w3 + M23 * w2 * w3)) / dN;
    double var = ex2 - mu * mu;
    double a = (double)g0[ch] / sqrt(var + (double)EPSB);
    g_a0[ch] = (float)a;
    g_c0[ch] = (float)((double)b0[ch] - mu * a);
}

// ---------------- scatter (no atomics) ----------------
__global__ void k_scatter(const float* __restrict__ pts, int N) {
    int i = blockIdx.x * blockDim.x + threadIdx.x;
    if (i >= N) return;
    const float* p = pts + (size_t)i * 5;
    float x = p[1], y = p[2], t = p[3], pol = p[4];
    int inv = g_inv[i];
    int pos = g_off[inv] + g_rank[i];
    g_feat[pos] = make_float4(x / 346.0f, y / 260.0f, t / 200.0f, pol);
}

// ---------------- per-segment reduction: tf32 MMA phase B ----------------
__global__ void __launch_bounds__(128, 4)
k_seg(const float* __restrict__ W0, const float* __restrict__ W1) {
    int tid  = threadIdx.x;
    int c    = tid & 31;       // phase-A channel
    int row  = tid >> 5;       // phase-A point row 0..3 (= warp id)
    int lane = tid & 31;
    int warp = tid >> 5;
    int grp  = lane >> 2;      // 0..7
    int qd   = lane & 3;       // 0..3
    int warpbase = warp * 32;  // this warp's 32 output channels

    // B fragments (tf32) for W1[:32, warp's 32 cols], held in registers
    unsigned bf[4][4][2];      // [ntile][kblk][2]
#pragma unroll
    for (int nt = 0; nt < 4; nt++) {
#pragma unroll
        for (int kb = 0; kb < 4; kb++) {
            int n = warpbase + nt * 8 + grp;
            bf[nt][kb][0] = to_tf32(W1[(kb * 8 + qd) * C1 + n]);
            bf[nt][kb][1] = to_tf32(W1[(kb * 8 + qd + 4) * C1 + n]);
        }
    }

    float w00 = W0[c], w01 = W0[C0 + c], w02 = W0[2 * C0 + c], w03 = W0[3 * C0 + c];
    float a0c = g_a0[c], c0c = g_c0[c];

    __shared__ __align__(16) float h0s[2][64 * RS];  // point-major: [pt][ch]
    __shared__ float pm[4][32], pM[4][32], ps[4][32];

    float ssqg[8];              // whole-kernel Σa² partials, per owned channel
#pragma unroll
    for (int s = 0; s < 8; s++) ssqg[s] = 0.0f;

    int buf = 0;

    for (int seg = blockIdx.x; seg < NSEG; seg += gridDim.x) {
        int cnt = g_cnt[seg];
        if (cnt == 0) continue;
        int off = g_off[seg];

        // prefetch next owned segment's first 64 points into L2 (overlaps this segment)
        {
            int nseg = seg + gridDim.x;
            if (nseg < NSEG && tid < 8) {
                int ncnt = g_cnt[nseg];
                if (tid * 8 < ncnt) pfL2(&g_feat[g_off[nseg] + tid * 8]);
            }
        }

        float lmin = INFINITY, lmax = -INFINITY, lsum = 0.0f;
        float minr[8], maxr[8];
#pragma unroll
        for (int s = 0; s < 8; s++) { minr[s] = INFINITY; maxr[s] = -INFINITY; }

        for (int chunk = 0; chunk < cnt; chunk += 64) {
            buf ^= 1;
            int m = min(64, cnt - chunk);
            int m16 = (m + 15) & ~15;
            // ---- phase A: h0 point-major; pad rows duplicate last point ----
            for (int p = row; p < m16; p += 4) {
                int pi = min(p, m - 1);
                float4 f = g_feat[off + chunk + pi];
                float h = f.x * w00 + f.y * w01 + f.z * w02 + f.w * w03;
                lmin = fminf(lmin, h);
                lmax = fmaxf(lmax, h);
                float sh = swishf(a0c * h + c0c);
                if (p < m) lsum += sh;
                h0s[buf][p * RS + c] = sh;
            }
            __syncthreads();
            // ---- phase B: tf32 MMA; no trailing sync (double buffer) ----
            const float* hp = &h0s[buf][0];
            int nmt = m16 >> 4;
            for (int mt = 0; mt < nmt; mt++) {
                float d[4][4];
#pragma unroll
                for (int nt = 0; nt < 4; nt++) {
                    d[nt][0] = 0.0f; d[nt][1] = 0.0f; d[nt][2] = 0.0f; d[nt][3] = 0.0f;
                }
                int r0 = mt * 16 + grp;
#pragma unroll
                for (int kb = 0; kb < 4; kb++) {
                    unsigned ua0 = to_tf32(hp[r0 * RS + kb * 8 + qd]);
                    unsigned ua1 = to_tf32(hp[(r0 + 8) * RS + kb * 8 + qd]);
                    unsigned ua2 = to_tf32(hp[r0 * RS + kb * 8 + qd + 4]);
                    unsigned ua3 = to_tf32(hp[(r0 + 8) * RS + kb * 8 + qd + 4]);
#pragma unroll
                    for (int nt = 0; nt < 4; nt++)
                        mma_tf32(d[nt][0], d[nt][1], d[nt][2], d[nt][3],
                                 ua0, ua1, ua2, ua3, bf[nt][kb][0], bf[nt][kb][1]);
                }
                bool v0 = r0 < m;
                bool v1 = (r0 + 8) < m;
#pragma unroll
                for (int nt = 0; nt < 4; nt++) {
#pragma unroll
                    for (int j = 0; j < 2; j++) {
                        int s = nt * 2 + j;
                        float x0 = d[nt][j];       // row r0
                        float x1 = d[nt][2 + j];   // row r0+8
                        minr[s] = fminf(minr[s], fminf(x0, x1));
                        maxr[s] = fmaxf(maxr[s], fmaxf(x0, x1));
                        if (v0) ssqg[s] = fmaf(x0, x0, ssqg[s]);
                        if (v1) ssqg[s] = fmaf(x1, x1, ssqg[s]);
                    }
                }
            }
        }

        // ---- phase-A m0 + Σh0 (needs all rows' partials) ----
        pm[row][c] = lmin;
        pM[row][c] = lmax;
        ps[row][c] = lsum;
        __syncthreads();
        if (tid < 32) {
            float mn = fminf(fminf(pm[0][tid], pm[1][tid]), fminf(pm[2][tid], pm[3][tid]));
            float mx = fmaxf(fmaxf(pM[0][tid], pM[1][tid]), fmaxf(pM[2][tid], pM[3][tid]));
            g_m0[seg * C0 + tid] = swish_seg_max(mn, mx, g_a0[tid], g_c0[tid]);
            g_sh0[seg * C0 + tid] = (ps[0][tid] + ps[1][tid]) + (ps[2][tid] + ps[3][tid]);
        }

        // ---- reduce min/max across the 8 row-threads (xor 4,8,16) ----
#pragma unroll
        for (int s = 0; s < 8; s++) {
#pragma unroll
            for (int dd = 4; dd <= 16; dd <<= 1) {
                minr[s] = fminf(minr[s], __shfl_xor_sync(0xFFFFFFFFu, minr[s], dd));
                maxr[s] = fmaxf(maxr[s], __shfl_xor_sync(0xFFFFFFFFu, maxr[s], dd));
            }
        }
        if (grp == 0) {
#pragma unroll
            for (int s = 0; s < 8; s++) {
                int ch = warpbase + (s >> 1) * 8 + 2 * qd + (s & 1);
                size_t ix = (size_t)seg * C1 + ch;
                g_amin[ix] = minr[s];
                g_amax[ix] = maxr[s];
            }
        }
        __syncthreads();
    }

    // ---- final: reduce whole-kernel Σa² and flush ----
#pragma unroll
    for (int s = 0; s < 8; s++) {
#pragma unroll
        for (int dd = 4; dd <= 16; dd <<= 1)
            ssqg[s] += __shfl_xor_sync(0xFFFFFFFFu, ssqg[s], dd);
        if (grp == 0) {
            int ch = warpbase + (s >> 1) * 8 + 2 * qd + (s & 1);
            atomicAdd(&g_ss1[ch], (double)ssqg[s]);
        }
    }
}

// ---------------- finalize per segment: B, Σa (linearity), m1 endpoints, BN1 sums ----------------
__global__ void __launch_bounds__(128)
k_fin(const float* __restrict__ W1) {
    int tid = threadIdx.x;
    float wlo[32], whi[32];
#pragma unroll
    for (int j = 0; j < 32; j++) wlo[j] = W1[j * C1 + tid];
#pragma unroll
    for (int j = 0; j < 32; j++) whi[j] = W1[(32 + j) * C1 + tid];

    __shared__ float m0s[32], sh0s[32];
    double dsum = 0.0, dssq = 0.0;

    for (int seg = blockIdx.x; seg < NSEG; seg += gridDim.x) {
        int cnt = g_cnt[seg];
        if (cnt == 0) continue;
        if (tid < 32) {
            m0s[tid] = g_m0[seg * C0 + tid];
            sh0s[tid] = g_sh0[seg * C0 + tid];
        }
        __syncthreads();
        float B = 0.0f, asum = 0.0f;
#pragma unroll
        for (int j = 0; j < 32; j++) {
            B = fmaf(m0s[j], whi[j], B);
            asum = fmaf(sh0s[j], wlo[j], asum);
        }
        size_t ix = (size_t)seg * C1 + tid;
        g_min1[ix] = g_amin[ix] + B;
        g_max1[ix] = g_amax[ix] + B;
        float fc = (float)cnt;
        dsum += (double)(asum + fc * B);
        dssq += (double)(2.0f * B * asum + fc * B * B);
        __syncthreads();
    }
    atomicAdd(&g_s1[tid], dsum);
    atomicAdd(&g_ss1[tid], dssq);
}

// ---------------- S1: bn1 affine ----------------
__global__ void k_s1(const float* __restrict__ g1, const float* __restrict__ b1, int N) {
    int ch = threadIdx.x;
    if (ch >= C1) return;
    double dN = (double)N;
    double mu = g_s1[ch] / dN;
    double var = g_ss1[ch] / dN - mu * mu;
    double a = (double)g1[ch] / sqrt(var + (double)EPSB);
    g_a1[ch] = (float)a;
    g_c1[ch] = (float)((double)b1[ch] - mu * a);
}

// ---------------- T2: resolve m1, scatter into dense ----------------
__global__ void k_t2() {
    int i = blockIdx.x * blockDim.x + threadIdx.x;
    if (i >= NSEG * C1) return;
    int ch = i & (C1 - 1);
    int seg = i >> 7;
    float val = 0.0f;
    if (g_cnt[seg] > 0) {
        float a = g_a1[ch], c = g_c1[ch];
        float pmin = g_min1[i], pmax = g_max1[i];
        val = fmaxf(swishf(a * pmin + c), swishf(a * pmax + c));
    }
    int cy = seg % GY;
    int r = seg / GY;
    int cx = r % GX;
    int b = r / GX;
    g_dense[((b * C1 + ch) * GY + cy) * GX + cx] = val;
}

// ---------------- R: bilinear resize, float4 stores ----------------
__global__ void k_resize(float* __restrict__ out, int total) {
    int i = blockIdx.x * blockDim.x + threadIdx.x;
    if (i * 4 >= total) return;
    int xg = i % 56;
    int yo = (i / 56) % 224;
    int bc = i / (56 * 224);

    const float sy = (GY - 1.0f) / 223.0f;
    const float sx = (GX - 1.0f) / 223.0f;
    float yy = (float)yo * sy;
    int y0 = (int)floorf(yy);
    int y1 = min(y0 + 1, GY - 1);
    float wy = yy - (float)y0;

    const float* d = g_dense + (size_t)bc * GY * GX;
    const float* r0p = d + y0 * GX;
    const float* r1p = d + y1 * GX;

    float4 res;
    float* rp = (float*)&res;
#pragma unroll
    for (int s = 0; s < 4; s++) {
        int xo = xg * 4 + s;
        float xx = (float)xo * sx;
        int x0 = (int)floorf(xx);
        int x1 = min(x0 + 1, GX - 1);
        float wx = xx - (float)x0;
        float d00 = r0p[x0], d01 = r0p[x1];
        float d10 = r1p[x0], d11 = r1p[x1];
        float xh0 = d00 * (1.0f - wy) + d10 * wy;
        float xh1 = d01 * (1.0f - wy) + d11 * wy;
        rp[s] = xh0 * (1.0f - wx) + xh1 * wx;
    }
    *reinterpret_cast<float4*>(out + (size_t)i * 4) = res;
}

// ---------------- launch ----------------
extern "C" void kernel_launch(void* const* d_in, const int* in_sizes, int n_in,
                              void* d_out, int out_size) {
    const float* pts = (const float*)d_in[1];
    const float* W0  = (const float*)d_in[2];
    const float* g0  = (const float*)d_in[3];
    const float* b0  = (const float*)d_in[4];
    const float* W1  = (const float*)d_in[5];
    const float* g1  = (const float*)d_in[6];
    const float* b1  = (const float*)d_in[7];
    float* out = (float*)d_out;
    int N = in_sizes[1] / 5;
    if (N > MAXN) N = MAXN;

    k_init<<<(NSEG + 255) / 256, 256>>>();
    k_p1<<<(N + 255) / 256, 256>>>(pts, N);
    k_scan<<<1, 1024>>>();
    k_s0<<<1, 32>>>(W0, g0, b0, N);
    k_scatter<<<(N + 255) / 256, 256>>>(pts, N);
    k_seg<<<NBLK, 128>>>(W0, W1);
    k_fin<<<NBLK, 128>>>(W1);
    k_s1<<<1, C1>>>(g1, b1, N);
    k_t2<<<(NSEG * C1 + 255) / 256, 256>>>();
    k_resize<<<(out_size / 4 + 255) / 256, 256>>>(out, out_size);
}

// round 16
// speedup vs baseline: 1.4538x; 1.0287x over previous
#include <cuda_runtime.h>
#include <cuda_bf16.h>
#include <math.h>

// ---------------- problem constants ----------------
#define GX 116
#define GY 87
#define BATCH 4
#define NSEG (BATCH * GX * GY)          // 40368
#define MAXN 1000000
#define C0 32
#define C1 128
#define EPSB 0.001f
#define RS 36                            // h0 row stride (floats), bank-conflict-free
#define NBLK 740                         // 148 SMs x 5 blocks

typedef unsigned long long ull;

// ---------------- scratch (__device__ globals; no allocation) ----------------
__device__ int    g_inv[MAXN];
__device__ int    g_rank[MAXN];
__device__ float4 g_feat[MAXN];          // segment-sorted packed features
__device__ int    g_cnt[NSEG];
__device__ int    g_off[NSEG];
__device__ float  g_amin[NSEG * C1];     // per-seg pre-B endpoints (exclusive owner)
__device__ float  g_amax[NSEG * C1];
__device__ float  g_m0[NSEG * C0];
__device__ float  g_sh0[NSEG * C0];      // per-seg sum of h0 (for Σa via linearity)
__device__ float  g_min1[NSEG * C1];
__device__ float  g_max1[NSEG * C1];
__device__ double g_mom[14];
__device__ double g_s1[C1];
__device__ double g_ss1[C1];
__device__ float  g_a0[C0], g_c0[C0];
__device__ float  g_a1[C1], g_c1[C1];
__device__ float  g_dense[BATCH * C1 * GY * GX];

// ---------------- helpers ----------------
__device__ __forceinline__ float swishf(float x) {
    return __fdividef(x, 1.0f + __expf(-x));
}
__device__ __forceinline__ float swish_seg_max(float pmin, float pmax, float a, float c) {
    return fmaxf(swishf(a * pmin + c), swishf(a * pmax + c));
}
__device__ __forceinline__ unsigned to_tf32(float f) {
    unsigned u;
    asm("cvt.rna.tf32.f32 %0, %1;" : "=r"(u) : "f"(f));
    return u;
}
__device__ __forceinline__ void mma_tf32(float& d0, float& d1, float& d2, float& d3,
                                         unsigned a0, unsigned a1, unsigned a2, unsigned a3,
                                         unsigned b0, unsigned b1) {
    asm volatile("mma.sync.aligned.m16n8k8.row.col.f32.tf32.tf32.f32 "
                 "{%0,%1,%2,%3}, {%4,%5,%6,%7}, {%8,%9}, {%0,%1,%2,%3};"
                 : "+f"(d0), "+f"(d1), "+f"(d2), "+f"(d3)
                 : "r"(a0), "r"(a1), "r"(a2), "r"(a3), "r"(b0), "r"(b1));
}
__device__ __forceinline__ void pfL2(const void* p) {
    asm volatile("prefetch.global.L2 [%0];" :: "l"(p));
}

// ---------------- init ----------------
__global__ void k_init() {
    int i = blockIdx.x * blockDim.x + threadIdx.x;
    if (i < NSEG) g_cnt[i] = 0;
    if (i < 14)   g_mom[i] = 0.0;
    if (i < C1)   { g_s1[i] = 0.0; g_ss1[i] = 0.0; }
}

// ---------------- P1: inv, rank, histogram, feature moments ----------------
__global__ void k_p1(const float* __restrict__ pts, int N) {
    __shared__ double smom[14];
    if (threadIdx.x < 14) smom[threadIdx.x] = 0.0;
    __syncthreads();

    int i = blockIdx.x * blockDim.x + threadIdx.x;
    float m[14];
#pragma unroll
    for (int k = 0; k < 14; k++) m[k] = 0.0f;

    if (i < N) {
        const float* p = pts + (size_t)i * 5;
        float b = p[0], x = p[1], y = p[2], t = p[3], pol = p[4];
        int cx = (int)floorf(x / 3.0f);
        int cy = (int)floorf(y / 3.0f);
        int bi = (int)b;
        int inv = (bi * GX + cx) * GY + cy;
        g_inv[i] = inv;
        g_rank[i] = atomicAdd(&g_cnt[inv], 1);
        float f0 = x / 346.0f, f1 = y / 260.0f, f2 = t / 200.0f, f3 = pol;
        m[0] = f0; m[1] = f1; m[2] = f2; m[3] = f3;
        m[4] = f0 * f0; m[5] = f0 * f1; m[6] = f0 * f2; m[7] = f0 * f3;
        m[8] = f1 * f1; m[9] = f1 * f2; m[10] = f1 * f3;
        m[11] = f2 * f2; m[12] = f2 * f3; m[13] = f3 * f3;
    }

#pragma unroll
    for (int k = 0; k < 14; k++) {
#pragma unroll
        for (int off = 16; off > 0; off >>= 1)
            m[k] += __shfl_down_sync(0xFFFFFFFFu, m[k], off);
    }
    if ((threadIdx.x & 31) == 0) {
#pragma unroll
        for (int k = 0; k < 14; k++) atomicAdd(&smom[k], (double)m[k]);
    }
    __syncthreads();
    if (threadIdx.x < 14) atomicAdd(&g_mom[threadIdx.x], smom[threadIdx.x]);
}

// ---------------- scan (+ fused bn0 affine at tail) ----------------
__global__ void k_scan(const float* __restrict__ W0, const float* __restrict__ g0,
                       const float* __restrict__ b0, int N) {
    __shared__ int partial[1024];
    const int PER = (NSEG + 1023) / 1024;
    int tid = threadIdx.x;
    int base = tid * PER;
    int s = 0;
    for (int k = 0; k < PER; k++) {
        int idx = base + k;
        if (idx < NSEG) s += g_cnt[idx];
    }
    partial[tid] = s;
    __syncthreads();
    for (int d = 1; d < 1024; d <<= 1) {
        int v = partial[tid];
        int add = (tid >= d) ? partial[tid - d] : 0;
        __syncthreads();
        partial[tid] = v + add;
        __syncthreads();
    }
    int run = (tid == 0) ? 0 : partial[tid - 1];
    for (int k = 0; k < PER; k++) {
        int idx = base + k;
        if (idx < NSEG) {
            g_off[idx] = run;
            run += g_cnt[idx];
        }
    }

    // fused S0: bn0 affine from moments (g_mom complete since k_p1 finished)
    if (tid < C0) {
        int ch = tid;
        double s0 = g_mom[0], s1 = g_mom[1], s2 = g_mom[2], s3 = g_mom[3];
        double M00 = g_mom[4], M01 = g_mom[5], M02 = g_mom[6], M03 = g_mom[7];
        double M11 = g_mom[8], M12 = g_mom[9], M13 = g_mom[10];
        double M22 = g_mom[11], M23 = g_mom[12], M33 = g_mom[13];
        double w0 = W0[ch], w1 = W0[C0 + ch], w2 = W0[2 * C0 + ch], w3 = W0[3 * C0 + ch];
        double dN = (double)N;
        double mu = (s0 * w0 + s1 * w1 + s2 * w2 + s3 * w3) / dN;
        double ex2 = (M00 * w0 * w0 + M11 * w1 * w1 + M22 * w2 * w2 + M33 * w3 * w3
                      + 2.0 * (M01 * w0 * w1 + M02 * w0 * w2 + M03 * w0 * w3
                               + M12 * w1 * w2 + M13 * w1 * w3 + M23 * w2 * w3)) / dN;
        double var = ex2 - mu * mu;
        double a = (double)g0[ch] / sqrt(var + (double)EPSB);
        g_a0[ch] = (float)a;
        g_c0[ch] = (float)((double)b0[ch] - mu * a);
    }
}

// ---------------- scatter (no atomics) ----------------
__global__ void k_scatter(const float* __restrict__ pts, int N) {
    int i = blockIdx.x * blockDim.x + threadIdx.x;
    if (i >= N) return;
    const float* p = pts + (size_t)i * 5;
    float x = p[1], y = p[2], t = p[3], pol = p[4];
    int inv = g_inv[i];
    int pos = g_off[inv] + g_rank[i];
    g_feat[pos] = make_float4(x / 346.0f, y / 260.0f, t / 200.0f, pol);
}

// ---------------- per-segment reduction: tf32 MMA phase B ----------------
__global__ void __launch_bounds__(128, 5)
k_seg(const float* __restrict__ W0, const float* __restrict__ W1) {
    int tid  = threadIdx.x;
    int c    = tid & 31;       // phase-A channel
    int row  = tid >> 5;       // phase-A point row 0..3 (= warp id)
    int lane = tid & 31;
    int warp = tid >> 5;
    int grp  = lane >> 2;      // 0..7
    int qd   = lane & 3;       // 0..3
    int warpbase = warp * 32;  // this warp's 32 output channels

    // B fragments (tf32) for W1[:32, warp's 32 cols], held in registers
    unsigned bf[4][4][2];      // [ntile][kblk][2]
#pragma unroll
    for (int nt = 0; nt < 4; nt++) {
#pragma unroll
        for (int kb = 0; kb < 4; kb++) {
            int n = warpbase + nt * 8 + grp;
            bf[nt][kb][0] = to_tf32(W1[(kb * 8 + qd) * C1 + n]);
            bf[nt][kb][1] = to_tf32(W1[(kb * 8 + qd + 4) * C1 + n]);
        }
    }

    float w00 = W0[c], w01 = W0[C0 + c], w02 = W0[2 * C0 + c], w03 = W0[3 * C0 + c];
    float a0c = g_a0[c], c0c = g_c0[c];

    __shared__ __align__(16) float h0s[2][64 * RS];  // point-major: [pt][ch]
    __shared__ float pm[4][32], pM[4][32], ps[4][32];

    float ssqg[8];              // whole-kernel Σa² partials, per owned channel
#pragma unroll
    for (int s = 0; s < 8; s++) ssqg[s] = 0.0f;

    int buf = 0;

    for (int seg = blockIdx.x; seg < NSEG; seg += gridDim.x) {
        int cnt = g_cnt[seg];
        if (cnt == 0) continue;
        int off = g_off[seg];

        // prefetch next owned segment's first 64 points into L2 (overlaps this segment)
        {
            int nseg = seg + gridDim.x;
            if (nseg < NSEG && tid < 8) {
                int ncnt = g_cnt[nseg];
                if (tid * 8 < ncnt) pfL2(&g_feat[g_off[nseg] + tid * 8]);
            }
        }

        float lmin = INFINITY, lmax = -INFINITY, lsum = 0.0f;
        float minr[8], maxr[8];
#pragma unroll
        for (int s = 0; s < 8; s++) { minr[s] = INFINITY; maxr[s] = -INFINITY; }

        for (int chunk = 0; chunk < cnt; chunk += 64) {
            buf ^= 1;
            int m = min(64, cnt - chunk);
            int m16 = (m + 15) & ~15;
            // ---- phase A: h0 point-major; pad rows duplicate last point ----
            for (int p = row; p < m16; p += 4) {
                int pi = min(p, m - 1);
                float4 f = g_feat[off + chunk + pi];
                float h = f.x * w00 + f.y * w01 + f.z * w02 + f.w * w03;
                lmin = fminf(lmin, h);
                lmax = fmaxf(lmax, h);
                float sh = swishf(a0c * h + c0c);
                if (p < m) lsum += sh;
                h0s[buf][p * RS + c] = sh;
            }
            __syncthreads();
            // ---- phase B: tf32 MMA; no trailing sync (double buffer) ----
            const float* hp = &h0s[buf][0];
            int nmt = m16 >> 4;
            for (int mt = 0; mt < nmt; mt++) {
                float d[4][4];
#pragma unroll
                for (int nt = 0; nt < 4; nt++) {
                    d[nt][0] = 0.0f; d[nt][1] = 0.0f; d[nt][2] = 0.0f; d[nt][3] = 0.0f;
                }
                int r0 = mt * 16 + grp;
#pragma unroll
                for (int kb = 0; kb < 4; kb++) {
                    unsigned ua0 = to_tf32(hp[r0 * RS + kb * 8 + qd]);
                    unsigned ua1 = to_tf32(hp[(r0 + 8) * RS + kb * 8 + qd]);
                    unsigned ua2 = to_tf32(hp[r0 * RS + kb * 8 + qd + 4]);
                    unsigned ua3 = to_tf32(hp[(r0 + 8) * RS + kb * 8 + qd + 4]);
#pragma unroll
                    for (int nt = 0; nt < 4; nt++)
                        mma_tf32(d[nt][0], d[nt][1], d[nt][2], d[nt][3],
                                 ua0, ua1, ua2, ua3, bf[nt][kb][0], bf[nt][kb][1]);
                }
                bool v0 = r0 < m;
                bool v1 = (r0 + 8) < m;
#pragma unroll
                for (int nt = 0; nt < 4; nt++) {
#pragma unroll
                    for (int j = 0; j < 2; j++) {
                        int s = nt * 2 + j;
                        float x0 = d[nt][j];       // row r0
                        float x1 = d[nt][2 + j];   // row r0+8
                        minr[s] = fminf(minr[s], fminf(x0, x1));
                        maxr[s] = fmaxf(maxr[s], fmaxf(x0, x1));
                        if (v0) ssqg[s] = fmaf(x0, x0, ssqg[s]);
                        if (v1) ssqg[s] = fmaf(x1, x1, ssqg[s]);
                    }
                }
            }
        }

        // ---- phase-A m0 + Σh0 (needs all rows' partials) ----
        pm[row][c] = lmin;
        pM[row][c] = lmax;
        ps[row][c] = lsum;
        __syncthreads();
        if (tid < 32) {
            float mn = fminf(fminf(pm[0][tid], pm[1][tid]), fminf(pm[2][tid], pm[3][tid]));
            float mx = fmaxf(fmaxf(pM[0][tid], pM[1][tid]), fmaxf(pM[2][tid], pM[3][tid]));
            g_m0[seg * C0 + tid] = swish_seg_max(mn, mx, g_a0[tid], g_c0[tid]);
            g_sh0[seg * C0 + tid] = (ps[0][tid] + ps[1][tid]) + (ps[2][tid] + ps[3][tid]);
        }

        // ---- reduce min/max across the 8 row-threads (xor 4,8,16) ----
#pragma unroll
        for (int s = 0; s < 8; s++) {
#pragma unroll
            for (int dd = 4; dd <= 16; dd <<= 1) {
                minr[s] = fminf(minr[s], __shfl_xor_sync(0xFFFFFFFFu, minr[s], dd));
                maxr[s] = fmaxf(maxr[s], __shfl_xor_sync(0xFFFFFFFFu, maxr[s], dd));
            }
        }
        if (grp == 0) {
#pragma unroll
            for (int s = 0; s < 8; s++) {
                int ch = warpbase + (s >> 1) * 8 + 2 * qd + (s & 1);
                size_t ix = (size_t)seg * C1 + ch;
                g_amin[ix] = minr[s];
                g_amax[ix] = maxr[s];
            }
        }
        __syncthreads();
    }

    // ---- final: reduce whole-kernel Σa² and flush ----
#pragma unroll
    for (int s = 0; s < 8; s++) {
#pragma unroll
        for (int dd = 4; dd <= 16; dd <<= 1)
            ssqg[s] += __shfl_xor_sync(0xFFFFFFFFu, ssqg[s], dd);
        if (grp == 0) {
            int ch = warpbase + (s >> 1) * 8 + 2 * qd + (s & 1);
            atomicAdd(&g_ss1[ch], (double)ssqg[s]);
        }
    }
}

// ---------------- finalize per segment: B, Σa (linearity), m1 endpoints, BN1 sums ----------------
__global__ void __launch_bounds__(128)
k_fin(const float* __restrict__ W1) {
    int tid = threadIdx.x;
    float wlo[32], whi[32];
#pragma unroll
    for (int j = 0; j < 32; j++) wlo[j] = W1[j * C1 + tid];
#pragma unroll
    for (int j = 0; j < 32; j++) whi[j] = W1[(32 + j) * C1 + tid];

    __shared__ float m0s[32], sh0s[32];
    double dsum = 0.0, dssq = 0.0;

    for (int seg = blockIdx.x; seg < NSEG; seg += gridDim.x) {
        int cnt = g_cnt[seg];
        if (cnt == 0) continue;
        if (tid < 32) {
            m0s[tid] = g_m0[seg * C0 + tid];
            sh0s[tid] = g_sh0[seg * C0 + tid];
        }
        __syncthreads();
        float B = 0.0f, asum = 0.0f;
#pragma unroll
        for (int j = 0; j < 32; j++) {
            B = fmaf(m0s[j], whi[j], B);
            asum = fmaf(sh0s[j], wlo[j], asum);
        }
        size_t ix = (size_t)seg * C1 + tid;
        g_min1[ix] = g_amin[ix] + B;
        g_max1[ix] = g_amax[ix] + B;
        float fc = (float)cnt;
        dsum += (double)(asum + fc * B);
        dssq += (double)(2.0f * B * asum + fc * B * B);
        __syncthreads();
    }
    atomicAdd(&g_s1[tid], dsum);
    atomicAdd(&g_ss1[tid], dssq);
}

// ---------------- S1: bn1 affine ----------------
__global__ void k_s1(const float* __restrict__ g1, const float* __restrict__ b1, int N) {
    int ch = threadIdx.x;
    if (ch >= C1) return;
    double dN = (double)N;
    double mu = g_s1[ch] / dN;
    double var = g_ss1[ch] / dN - mu * mu;
    double a = (double)g1[ch] / sqrt(var + (double)EPSB);
    g_a1[ch] = (float)a;
    g_c1[ch] = (float)((double)b1[ch] - mu * a);
}

// ---------------- T2: resolve m1, scatter into dense ----------------
__global__ void k_t2() {
    int i = blockIdx.x * blockDim.x + threadIdx.x;
    if (i >= NSEG * C1) return;
    int ch = i & (C1 - 1);
    int seg = i >> 7;
    float val = 0.0f;
    if (g_cnt[seg] > 0) {
        float a = g_a1[ch], c = g_c1[ch];
        float pmin = g_min1[i], pmax = g_max1[i];
        val = fmaxf(swishf(a * pmin + c), swishf(a * pmax + c));
    }
    int cy = seg % GY;
    int r = seg / GY;
    int cx = r % GX;
    int b = r / GX;
    g_dense[((b * C1 + ch) * GY + cy) * GX + cx] = val;
}

// ---------------- R: bilinear resize, float4 stores ----------------
__global__ void k_resize(float* __restrict__ out, int total) {
    int i = blockIdx.x * blockDim.x + threadIdx.x;
    if (i * 4 >= total) return;
    int xg = i % 56;
    int yo = (i / 56) % 224;
    int bc = i / (56 * 224);

    const float sy = (GY - 1.0f) / 223.0f;
    const float sx = (GX - 1.0f) / 223.0f;
    float yy = (float)yo * sy;
    int y0 = (int)floorf(yy);
    int y1 = min(y0 + 1, GY - 1);
    float wy = yy - (float)y0;

    const float* d = g_dense + (size_t)bc * GY * GX;
    const float* r0p = d + y0 * GX;
    const float* r1p = d + y1 * GX;

    float4 res;
    float* rp = (float*)&res;
#pragma unroll
    for (int s = 0; s < 4; s++) {
        int xo = xg * 4 + s;
        float xx = (float)xo * sx;
        int x0 = (int)floorf(xx);
        int x1 = min(x0 + 1, GX - 1);
        float wx = xx - (float)x0;
        float d00 = r0p[x0], d01 = r0p[x1];
        float d10 = r1p[x0], d11 = r1p[x1];
        float xh0 = d00 * (1.0f - wy) + d10 * wy;
        float xh1 = d01 * (1.0f - wy) + d11 * wy;
        rp[s] = xh0 * (1.0f - wx) + xh1 * wx;
    }
    *reinterpret_cast<float4*>(out + (size_t)i * 4) = res;
}

// ---------------- launch ----------------
extern "C" void kernel_launch(void* const* d_in, const int* in_sizes, int n_in,
                              void* d_out, int out_size) {
    const float* pts = (const float*)d_in[1];
    const float* W0  = (const float*)d_in[2];
    const float* g0  = (const float*)d_in[3];
    const float* b0  = (const float*)d_in[4];
    const float* W1  = (const float*)d_in[5];
    const float* g1  = (const float*)d_in[6];
    const float* b1  = (const float*)d_in[7];
    float* out = (float*)d_out;
    int N = in_sizes[1] / 5;
    if (N > MAXN) N = MAXN;

    k_init<<<(NSEG + 255) / 256, 256>>>();
    k_p1<<<(N + 255) / 256, 256>>>(pts, N);
    k_scan<<<1, 1024>>>(W0, g0, b0, N);
    k_scatter<<<(N + 255) / 256, 256>>>(pts, N);
    k_seg<<<NBLK, 128>>>(W0, W1);
    k_fin<<<NBLK, 128>>>(W1);
    k_s1<<<1, C1>>>(g1, b1, N);
    k_t2<<<(NSEG * C1 + 255) / 256, 256>>>();
    k_resize<<<(out_size / 4 + 255) / 256, 256>>>(out, out_size);
}

// round 17
// speedup vs baseline: 1.5560x; 1.0703x over previous
#include <cuda_runtime.h>
#include <cuda_bf16.h>
#include <math.h>

// ---------------- problem constants ----------------
#define GX 116
#define GY 87
#define BATCH 4
#define NSEG (BATCH * GX * GY)          // 40368
#define MAXN 1000000
#define C0 32
#define C1 128
#define EPSB 0.001f
#define RS 36                            // h0 row stride (floats), bank-conflict-free
#define NBLK 740                         // 148 SMs x 5 blocks

typedef unsigned long long ull;

// ---------------- scratch (__device__ globals; no allocation) ----------------
__device__ int    g_inv[MAXN];
__device__ int    g_rank[MAXN];
__device__ float4 g_feat[MAXN];          // segment-sorted packed features
__device__ int    g_cnt[NSEG];
__device__ int    g_off[NSEG];
__device__ float  g_amin[NSEG * C1];     // per-seg pre-B endpoints (exclusive owner)
__device__ float  g_amax[NSEG * C1];
__device__ float  g_m0[NSEG * C0];
__device__ float  g_sh0[NSEG * C0];      // per-seg sum of h0 (for Σa via linearity)
__device__ float  g_min1[NSEG * C1];
__device__ float  g_max1[NSEG * C1];
__device__ double g_mom[14];
__device__ double g_s1[C1];
__device__ double g_ss1[C1];
__device__ float  g_a0[C0], g_c0[C0];
__device__ float  g_a1[C1], g_c1[C1];
__device__ float  g_dense[BATCH * C1 * GY * GX];

// ---------------- helpers ----------------
__device__ __forceinline__ float swishf(float x) {
    return __fdividef(x, 1.0f + __expf(-x));
}
__device__ __forceinline__ float swish_seg_max(float pmin, float pmax, float a, float c) {
    return fmaxf(swishf(a * pmin + c), swishf(a * pmax + c));
}
__device__ __forceinline__ unsigned to_tf32(float f) {
    unsigned u;
    asm("cvt.rna.tf32.f32 %0, %1;" : "=r"(u) : "f"(f));
    return u;
}
__device__ __forceinline__ void mma_tf32(float& d0, float& d1, float& d2, float& d3,
                                         unsigned a0, unsigned a1, unsigned a2, unsigned a3,
                                         unsigned b0, unsigned b1) {
    asm volatile("mma.sync.aligned.m16n8k8.row.col.f32.tf32.tf32.f32 "
                 "{%0,%1,%2,%3}, {%4,%5,%6,%7}, {%8,%9}, {%0,%1,%2,%3};"
                 : "+f"(d0), "+f"(d1), "+f"(d2), "+f"(d3)
                 : "r"(a0), "r"(a1), "r"(a2), "r"(a3), "r"(b0), "r"(b1));
}
__device__ __forceinline__ void pfL2(const void* p) {
    asm volatile("prefetch.global.L2 [%0];" :: "l"(p));
}

// ---------------- init ----------------
__global__ void k_init() {
    int i = blockIdx.x * blockDim.x + threadIdx.x;
    if (i < NSEG) g_cnt[i] = 0;
    if (i < 14)   g_mom[i] = 0.0;
    if (i < C1)   { g_s1[i] = 0.0; g_ss1[i] = 0.0; }
}

// ---------------- P1: inv, rank, histogram, feature moments (4 pts/thread) ----------------
__global__ void k_p1(const float* __restrict__ pts, int N) {
    __shared__ double smom[14];
    if (threadIdx.x < 14) smom[threadIdx.x] = 0.0;
    __syncthreads();

    int base = (blockIdx.x * blockDim.x + threadIdx.x) * 4;
    float m[14];
#pragma unroll
    for (int k = 0; k < 14; k++) m[k] = 0.0f;

    float px[4], py[4], pt_[4], pp[4];
    int np = 0;
    if (base + 4 <= N) {
        const float4* q = reinterpret_cast<const float4*>(pts + (size_t)base * 5);
        float4 q0 = q[0], q1 = q[1], q2 = q[2], q3 = q[3], q4 = q[4];
        // point k fields: [b, x, y, t, p]
        px[0] = q0.y; py[0] = q0.z; pt_[0] = q0.w; pp[0] = q1.x;
        px[1] = q1.z; py[1] = q1.w; pt_[1] = q2.x; pp[1] = q2.y;
        px[2] = q2.w; py[2] = q3.x; pt_[2] = q3.y; pp[2] = q3.z;
        px[3] = q4.x; py[3] = q4.y; pt_[3] = q4.z; pp[3] = q4.w;
        float pb[4] = {q0.x, q1.y, q2.z, q3.w};
        np = 4;
#pragma unroll
        for (int k = 0; k < 4; k++) {
            int i = base + k;
            int cx = (int)floorf(px[k] / 3.0f);
            int cy = (int)floorf(py[k] / 3.0f);
            int bi = (int)pb[k];
            int inv = (bi * GX + cx) * GY + cy;
            g_inv[i] = inv;
            g_rank[i] = atomicAdd(&g_cnt[inv], 1);
        }
    } else if (base < N) {
        for (int k = 0; k < 4 && base + k < N; k++) {
            const float* p = pts + (size_t)(base + k) * 5;
            float b = p[0];
            px[k] = p[1]; py[k] = p[2]; pt_[k] = p[3]; pp[k] = p[4];
            int cx = (int)floorf(px[k] / 3.0f);
            int cy = (int)floorf(py[k] / 3.0f);
            int bi = (int)b;
            int inv = (bi * GX + cx) * GY + cy;
            g_inv[base + k] = inv;
            g_rank[base + k] = atomicAdd(&g_cnt[inv], 1);
            np = k + 1;
        }
    }

    for (int k = 0; k < np; k++) {
        float f0 = px[k] / 346.0f, f1 = py[k] / 260.0f, f2 = pt_[k] / 200.0f, f3 = pp[k];
        m[0] += f0; m[1] += f1; m[2] += f2; m[3] += f3;
        m[4] += f0 * f0; m[5] += f0 * f1; m[6] += f0 * f2; m[7] += f0 * f3;
        m[8] += f1 * f1; m[9] += f1 * f2; m[10] += f1 * f3;
        m[11] += f2 * f2; m[12] += f2 * f3; m[13] += f3 * f3;
    }

#pragma unroll
    for (int k = 0; k < 14; k++) {
#pragma unroll
        for (int off = 16; off > 0; off >>= 1)
            m[k] += __shfl_down_sync(0xFFFFFFFFu, m[k], off);
    }
    if ((threadIdx.x & 31) == 0) {
#pragma unroll
        for (int k = 0; k < 14; k++) atomicAdd(&smom[k], (double)m[k]);
    }
    __syncthreads();
    if (threadIdx.x < 14) atomicAdd(&g_mom[threadIdx.x], smom[threadIdx.x]);
}

// ---------------- scan (+ fused bn0 affine at tail) ----------------
__global__ void k_scan(const float* __restrict__ W0, const float* __restrict__ g0,
                       const float* __restrict__ b0, int N) {
    __shared__ int partial[1024];
    const int PER = (NSEG + 1023) / 1024;
    int tid = threadIdx.x;
    int base = tid * PER;
    int s = 0;
    for (int k = 0; k < PER; k++) {
        int idx = base + k;
        if (idx < NSEG) s += g_cnt[idx];
    }
    partial[tid] = s;
    __syncthreads();
    for (int d = 1; d < 1024; d <<= 1) {
        int v = partial[tid];
        int add = (tid >= d) ? partial[tid - d] : 0;
        __syncthreads();
        partial[tid] = v + add;
        __syncthreads();
    }
    int run = (tid == 0) ? 0 : partial[tid - 1];
    for (int k = 0; k < PER; k++) {
        int idx = base + k;
        if (idx < NSEG) {
            g_off[idx] = run;
            run += g_cnt[idx];
        }
    }

    // fused S0: bn0 affine from moments
    if (tid < C0) {
        int ch = tid;
        double s0 = g_mom[0], s1 = g_mom[1], s2 = g_mom[2], s3 = g_mom[3];
        double M00 = g_mom[4], M01 = g_mom[5], M02 = g_mom[6], M03 = g_mom[7];
        double M11 = g_mom[8], M12 = g_mom[9], M13 = g_mom[10];
        double M22 = g_mom[11], M23 = g_mom[12], M33 = g_mom[13];
        double w0 = W0[ch], w1 = W0[C0 + ch], w2 = W0[2 * C0 + ch], w3 = W0[3 * C0 + ch];
        double dN = (double)N;
        double mu = (s0 * w0 + s1 * w1 + s2 * w2 + s3 * w3) / dN;
        double ex2 = (M00 * w0 * w0 + M11 * w1 * w1 + M22 * w2 * w2 + M33 * w3 * w3
                      + 2.0 * (M01 * w0 * w1 + M02 * w0 * w2 + M03 * w0 * w3
                               + M12 * w1 * w2 + M13 * w1 * w3 + M23 * w2 * w3)) / dN;
        double var = ex2 - mu * mu;
        double a = (double)g0[ch] / sqrt(var + (double)EPSB);
        g_a0[ch] = (float)a;
        g_c0[ch] = (float)((double)b0[ch] - mu * a);
    }
}

// ---------------- scatter (no atomics; 4 pts/thread, float4 loads) ----------------
__global__ void k_scatter(const float* __restrict__ pts, int N) {
    int base = (blockIdx.x * blockDim.x + threadIdx.x) * 4;
    if (base >= N) return;
    if (base + 4 <= N) {
        const float4* q = reinterpret_cast<const float4*>(pts + (size_t)base * 5);
        float4 q0 = q[0], q1 = q[1], q2 = q[2], q3 = q[3], q4 = q[4];
        float px[4] = {q0.y, q1.z, q2.w, q4.x};
        float py[4] = {q0.z, q1.w, q3.x, q4.y};
        float pt_[4] = {q0.w, q2.x, q3.y, q4.z};
        float pp[4] = {q1.x, q2.y, q3.z, q4.w};
#pragma unroll
        for (int k = 0; k < 4; k++) {
            int i = base + k;
            int inv = g_inv[i];
            int pos = g_off[inv] + g_rank[i];
            g_feat[pos] = make_float4(px[k] / 346.0f, py[k] / 260.0f, pt_[k] / 200.0f, pp[k]);
        }
    } else {
        for (int k = 0; k < 4 && base + k < N; k++) {
            const float* p = pts + (size_t)(base + k) * 5;
            int i = base + k;
            int inv = g_inv[i];
            int pos = g_off[inv] + g_rank[i];
            g_feat[pos] = make_float4(p[1] / 346.0f, p[2] / 260.0f, p[3] / 200.0f, p[4]);
        }
    }
}

// ---------------- per-segment reduction: tf32 MMA phase B ----------------
__global__ void __launch_bounds__(128, 5)
k_seg(const float* __restrict__ W0, const float* __restrict__ W1) {
    int tid  = threadIdx.x;
    int c    = tid & 31;       // phase-A channel
    int row  = tid >> 5;       // phase-A point row 0..3 (= warp id)
    int lane = tid & 31;
    int warp = tid >> 5;
    int grp  = lane >> 2;      // 0..7
    int qd   = lane & 3;       // 0..3
    int warpbase = warp * 32;  // this warp's 32 output channels

    // B fragments (tf32) for W1[:32, warp's 32 cols], held in registers
    unsigned bf[4][4][2];      // [ntile][kblk][2]
#pragma unroll
    for (int nt = 0; nt < 4; nt++) {
#pragma unroll
        for (int kb = 0; kb < 4; kb++) {
            int n = warpbase + nt * 8 + grp;
            bf[nt][kb][0] = to_tf32(W1[(kb * 8 + qd) * C1 + n]);
            bf[nt][kb][1] = to_tf32(W1[(kb * 8 + qd + 4) * C1 + n]);
        }
    }

    float w00 = W0[c], w01 = W0[C0 + c], w02 = W0[2 * C0 + c], w03 = W0[3 * C0 + c];
    float a0c = g_a0[c], c0c = g_c0[c];

    __shared__ __align__(16) float h0s[2][64 * RS];  // point-major: [pt][ch]
    __shared__ float pm[4][32], pM[4][32], ps[4][32];

    float ssqg[8];              // whole-kernel Σa² partials, per owned channel
#pragma unroll
    for (int s = 0; s < 8; s++) ssqg[s] = 0.0f;

    int buf = 0;

    for (int seg = blockIdx.x; seg < NSEG; seg += gridDim.x) {
        int cnt = g_cnt[seg];
        if (cnt == 0) continue;
        int off = g_off[seg];

        // prefetch next owned segment's first 64 points into L2
        {
            int nseg = seg + gridDim.x;
            if (nseg < NSEG && tid < 8) {
                int ncnt = g_cnt[nseg];
                if (tid * 8 < ncnt) pfL2(&g_feat[g_off[nseg] + tid * 8]);
            }
        }

        float lmin = INFINITY, lmax = -INFINITY, lsum = 0.0f;
        float minr[8], maxr[8];
#pragma unroll
        for (int s = 0; s < 8; s++) { minr[s] = INFINITY; maxr[s] = -INFINITY; }

        for (int chunk = 0; chunk < cnt; chunk += 64) {
            buf ^= 1;
            int m = min(64, cnt - chunk);
            int m16 = (m + 15) & ~15;
            // ---- phase A: h0 point-major; pad rows duplicate last point ----
            for (int p = row; p < m16; p += 4) {
                int pi = min(p, m - 1);
                float4 f = g_feat[off + chunk + pi];
                float h = f.x * w00 + f.y * w01 + f.z * w02 + f.w * w03;
                lmin = fminf(lmin, h);
                lmax = fmaxf(lmax, h);
                float sh = swishf(a0c * h + c0c);
                if (p < m) lsum += sh;
                h0s[buf][p * RS + c] = sh;
            }
            __syncthreads();
            // ---- phase B: tf32 MMA; no trailing sync (double buffer) ----
            const float* hp = &h0s[buf][0];
            int nmt = m16 >> 4;
            for (int mt = 0; mt < nmt; mt++) {
                float d[4][4];
#pragma unroll
                for (int nt = 0; nt < 4; nt++) {
                    d[nt][0] = 0.0f; d[nt][1] = 0.0f; d[nt][2] = 0.0f; d[nt][3] = 0.0f;
                }
                int r0 = mt * 16 + grp;
#pragma unroll
                for (int kb = 0; kb < 4; kb++) {
                    unsigned ua0 = to_tf32(hp[r0 * RS + kb * 8 + qd]);
                    unsigned ua1 = to_tf32(hp[(r0 + 8) * RS + kb * 8 + qd]);
                    unsigned ua2 = to_tf32(hp[r0 * RS + kb * 8 + qd + 4]);
                    unsigned ua3 = to_tf32(hp[(r0 + 8) * RS + kb * 8 + qd + 4]);
#pragma unroll
                    for (int nt = 0; nt < 4; nt++)
                        mma_tf32(d[nt][0], d[nt][1], d[nt][2], d[nt][3],
                                 ua0, ua1, ua2, ua3, bf[nt][kb][0], bf[nt][kb][1]);
                }
                bool v0 = r0 < m;
                bool v1 = (r0 + 8) < m;
#pragma unroll
                for (int nt = 0; nt < 4; nt++) {
#pragma unroll
                    for (int j = 0; j < 2; j++) {
                        int s = nt * 2 + j;
                        float x0 = d[nt][j];       // row r0
                        float x1 = d[nt][2 + j];   // row r0+8
                        minr[s] = fminf(minr[s], fminf(x0, x1));
                        maxr[s] = fmaxf(maxr[s], fmaxf(x0, x1));
                        if (v0) ssqg[s] = fmaf(x0, x0, ssqg[s]);
                        if (v1) ssqg[s] = fmaf(x1, x1, ssqg[s]);
                    }
                }
            }
        }

        // ---- phase-A m0 + Σh0 (needs all rows' partials) ----
        pm[row][c] = lmin;
        pM[row][c] = lmax;
        ps[row][c] = lsum;
        __syncthreads();
        if (tid < 32) {
            float mn = fminf(fminf(pm[0][tid], pm[1][tid]), fminf(pm[2][tid], pm[3][tid]));
            float mx = fmaxf(fmaxf(pM[0][tid], pM[1][tid]), fmaxf(pM[2][tid], pM[3][tid]));
            g_m0[seg * C0 + tid] = swish_seg_max(mn, mx, g_a0[tid], g_c0[tid]);
            g_sh0[seg * C0 + tid] = (ps[0][tid] + ps[1][tid]) + (ps[2][tid] + ps[3][tid]);
        }

        // ---- reduce min/max across the 8 row-threads (xor 4,8,16) ----
#pragma unroll
        for (int s = 0; s < 8; s++) {
#pragma unroll
            for (int dd = 4; dd <= 16; dd <<= 1) {
                minr[s] = fminf(minr[s], __shfl_xor_sync(0xFFFFFFFFu, minr[s], dd));
                maxr[s] = fmaxf(maxr[s], __shfl_xor_sync(0xFFFFFFFFu, maxr[s], dd));
            }
        }
        if (grp == 0) {
#pragma unroll
            for (int s = 0; s < 8; s++) {
                int ch = warpbase + (s >> 1) * 8 + 2 * qd + (s & 1);
                size_t ix = (size_t)seg * C1 + ch;
                g_amin[ix] = minr[s];
                g_amax[ix] = maxr[s];
            }
        }
        // no trailing __syncthreads: pm/pM/ps next written after the next
        // segment's first chunk barrier; h0s reuse is two barriers away.
    }

    // ---- final: reduce whole-kernel Σa² and flush ----
#pragma unroll
    for (int s = 0; s < 8; s++) {
#pragma unroll
        for (int dd = 4; dd <= 16; dd <<= 1)
            ssqg[s] += __shfl_xor_sync(0xFFFFFFFFu, ssqg[s], dd);
        if (grp == 0) {
            int ch = warpbase + (s >> 1) * 8 + 2 * qd + (s & 1);
            atomicAdd(&g_ss1[ch], (double)ssqg[s]);
        }
    }
}

// ---------------- finalize per segment: B, Σa (linearity), m1 endpoints, BN1 sums ----------------
__global__ void __launch_bounds__(128)
k_fin(const float* __restrict__ W1) {
    int tid = threadIdx.x;
    float wlo[32], whi[32];
#pragma unroll
    for (int j = 0; j < 32; j++) wlo[j] = W1[j * C1 + tid];
#pragma unroll
    for (int j = 0; j < 32; j++) whi[j] = W1[(32 + j) * C1 + tid];

    __shared__ float m0s[32], sh0s[32];
    double dsum = 0.0, dssq = 0.0;

    for (int seg = blockIdx.x; seg < NSEG; seg += gridDim.x) {
        int cnt = g_cnt[seg];
        if (cnt == 0) continue;
        if (tid < 32) {
            m0s[tid] = g_m0[seg * C0 + tid];
            sh0s[tid] = g_sh0[seg * C0 + tid];
        }
        __syncthreads();
        float B = 0.0f, asum = 0.0f;
#pragma unroll
        for (int j = 0; j < 32; j++) {
            B = fmaf(m0s[j], whi[j], B);
            asum = fmaf(sh0s[j], wlo[j], asum);
        }
        size_t ix = (size_t)seg * C1 + tid;
        g_min1[ix] = g_amin[ix] + B;
        g_max1[ix] = g_amax[ix] + B;
        float fc = (float)cnt;
        dsum += (double)(asum + fc * B);
        dssq += (double)(2.0f * B * asum + fc * B * B);
        __syncthreads();
    }
    atomicAdd(&g_s1[tid], dsum);
    atomicAdd(&g_ss1[tid], dssq);
}

// ---------------- S1: bn1 affine ----------------
__global__ void k_s1(const float* __restrict__ g1, const float* __restrict__ b1, int N) {
    int ch = threadIdx.x;
    if (ch >= C1) return;
    double dN = (double)N;
    double mu = g_s1[ch] / dN;
    double var = g_ss1[ch] / dN - mu * mu;
    double a = (double)g1[ch] / sqrt(var + (double)EPSB);
    g_a1[ch] = (float)a;
    g_c1[ch] = (float)((double)b1[ch] - mu * a);
}

// ---------------- T2: resolve m1, scatter into dense ----------------
__global__ void k_t2() {
    int i = blockIdx.x * blockDim.x + threadIdx.x;
    if (i >= NSEG * C1) return;
    int ch = i & (C1 - 1);
    int seg = i >> 7;
    float val = 0.0f;
    if (g_cnt[seg] > 0) {
        float a = g_a1[ch], c = g_c1[ch];
        float pmin = g_min1[i], pmax = g_max1[i];
        val = fmaxf(swishf(a * pmin + c), swishf(a * pmax + c));
    }
    int cy = seg % GY;
    int r = seg / GY;
    int cx = r % GX;
    int b = r / GX;
    g_dense[((b * C1 + ch) * GY + cy) * GX + cx] = val;
}

// ---------------- R: bilinear resize, float4 stores ----------------
__global__ void k_resize(float* __restrict__ out, int total) {
    int i = blockIdx.x * blockDim.x + threadIdx.x;
    if (i * 4 >= total) return;
    int xg = i % 56;
    int yo = (i / 56) % 224;
    int bc = i / (56 * 224);

    const float sy = (GY - 1.0f) / 223.0f;
    const float sx = (GX - 1.0f) / 223.0f;
    float yy = (float)yo * sy;
    int y0 = (int)floorf(yy);
    int y1 = min(y0 + 1, GY - 1);
    float wy = yy - (float)y0;

    const float* d = g_dense + (size_t)bc * GY * GX;
    const float* r0p = d + y0 * GX;
    const float* r1p = d + y1 * GX;

    float4 res;
    float* rp = (float*)&res;
#pragma unroll
    for (int s = 0; s < 4; s++) {
        int xo = xg * 4 + s;
        float xx = (float)xo * sx;
        int x0 = (int)floorf(xx);
        int x1 = min(x0 + 1, GX - 1);
        float wx = xx - (float)x0;
        float d00 = r0p[x0], d01 = r0p[x1];
        float d10 = r1p[x0], d11 = r1p[x1];
        float xh0 = d00 * (1.0f - wy) + d10 * wy;
        float xh1 = d01 * (1.0f - wy) + d11 * wy;
        rp[s] = xh0 * (1.0f - wx) + xh1 * wx;
    }
    *reinterpret_cast<float4*>(out + (size_t)i * 4) = res;
}

// ---------------- launch ----------------
extern "C" void kernel_launch(void* const* d_in, const int* in_sizes, int n_in,
                              void* d_out, int out_size) {
    const float* pts = (const float*)d_in[1];
    const float* W0  = (const float*)d_in[2];
    const float* g0  = (const float*)d_in[3];
    const float* b0  = (const float*)d_in[4];
    const float* W1  = (const float*)d_in[5];
    const float* g1  = (const float*)d_in[6];
    const float* b1  = (const float*)d_in[7];
    float* out = (float*)d_out;
    int N = in_sizes[1] / 5;
    if (N > MAXN) N = MAXN;

    int n4 = (N + 3) / 4;
    k_init<<<(NSEG + 255) / 256, 256>>>();
    k_p1<<<(n4 + 255) / 256, 256>>>(pts, N);
    k_scan<<<1, 1024>>>(W0, g0, b0, N);
    k_scatter<<<(n4 + 255) / 256, 256>>>(pts, N);
    k_seg<<<NBLK, 128>>>(W0, W1);
    k_fin<<<NBLK, 128>>>(W1);
    k_s1<<<1, C1>>>(g1, b1, N);
    k_t2<<<(NSEG * C1 + 255) / 256, 256>>>();
    k_resize<<<(out_size / 4 + 255) / 256, 256>>>(out, out_size);
}